// round 6
// baseline (speedup 1.0000x reference)
#include <cuda_runtime.h>
#include <cuda_bf16.h>
#include <mma.h>
#include <cstdint>
#include <cstddef>

using namespace nvcuda;

// ---------------------------------------------------------------------------
// Problem: N=4096, D=128, R=8, OUT=128, B=4096
//   out[m, o] = e_m . selfK[:,o] + sum_{r,n} adj[r, idx_m, n] * WT[r*4096+n, o]
//   WT[r*4096+n, o] = sum_d emb[n,d] * relK[r,d,o]
//   m in [0,8192): m<4096 -> head (idx=head_idx, e=head_e), else tail.
// Inputs (metadata order):
//   0 embeddings f32 [4096,128]
//   1 head_idx   i32 [4096]
//   2 head_e     f32 [4096,128]
//   3 tail_idx   i32 [4096]
//   4 tail_e     f32 [4096,128]
//   5 adj_mats   f32 [8,4096,4096]
//   6 relation_kernel f32 [8,128,128]
//   7 self_kernel     f32 [128,128]
// Output: f32 [2,4096,128] (head then tail)
// ---------------------------------------------------------------------------

#define NN       4096
#define DD       128
#define RR       8
#define OUTD     128

// 16 MB scratch for WT (device global: allowed; no allocation)
__device__ float g_WT[RR * NN * OUTD];

// ---------------------------------------------------------------------------
// Kernel 0: zero the output (it is poisoned to 0xAA before timing)
// ---------------------------------------------------------------------------
__global__ void zero_kernel(float* __restrict__ out, int n) {
    int i = blockIdx.x * blockDim.x + threadIdx.x;
    if (i < n) out[i] = 0.0f;
}

// ---------------------------------------------------------------------------
// Kernel 1: WT[r*4096+n][o] = sum_d emb[n][d] * relK[r][d][o]   (fp32 exact)
// grid: (32 n-tiles, 8 r), 256 threads, 128x128 tile, thread micro-tile 8x8.
// ---------------------------------------------------------------------------
__global__ __launch_bounds__(256) void wt_kernel(
    const float* __restrict__ emb,     // [4096,128]
    const float* __restrict__ relK)    // [8,128,128]
{
    __shared__ float At[32 * 129];     // transposed A tile: [d][n], stride 129
    __shared__ float Bsh[32 * 132];    // B tile: [d][o], stride 132

    const int r  = blockIdx.y;
    const int n0 = blockIdx.x * 128;
    const int tid = threadIdx.x;
    const int ty = tid >> 4;           // 0..15 -> rows ty*8..ty*8+7
    const int tx = tid & 15;           // 0..15 -> cols tx*4..+3 and 64+tx*4..+3

    const float* B0 = relK + (size_t)r * DD * OUTD;

    float acc[8][8];
#pragma unroll
    for (int i = 0; i < 8; i++)
#pragma unroll
        for (int j = 0; j < 8; j++) acc[i][j] = 0.0f;

    for (int k0 = 0; k0 < DD; k0 += 32) {
        __syncthreads();
        // load A tile transposed: emb[n0+row][k0+d] -> At[d][row]
#pragma unroll
        for (int e = tid; e < 128 * 32; e += 256) {
            int row = e >> 5;          // 0..127 (n)
            int d   = e & 31;          // 0..31
            At[d * 129 + row] = emb[(size_t)(n0 + row) * DD + k0 + d];
        }
        // load B tile: relK[r][k0+d][o] -> Bsh[d][o]
#pragma unroll
        for (int e = tid; e < 32 * 128; e += 256) {
            int d = e >> 7;
            int o = e & 127;
            Bsh[d * 132 + o] = B0[(size_t)(k0 + d) * OUTD + o];
        }
        __syncthreads();

#pragma unroll
        for (int kk = 0; kk < 32; kk++) {
            float a[8];
#pragma unroll
            for (int i = 0; i < 8; i++) a[i] = At[kk * 129 + ty * 8 + i];
            float4 v0 = *(const float4*)&Bsh[kk * 132 + tx * 4];
            float4 v1 = *(const float4*)&Bsh[kk * 132 + 64 + tx * 4];
            float b[8] = {v0.x, v0.y, v0.z, v0.w, v1.x, v1.y, v1.z, v1.w};
#pragma unroll
            for (int i = 0; i < 8; i++)
#pragma unroll
                for (int j = 0; j < 8; j++)
                    acc[i][j] = fmaf(a[i], b[j], acc[i][j]);
        }
    }

    // write out
#pragma unroll
    for (int i = 0; i < 8; i++) {
        size_t row = (size_t)r * NN + n0 + ty * 8 + i;
        float4 w0 = make_float4(acc[i][0], acc[i][1], acc[i][2], acc[i][3]);
        float4 w1 = make_float4(acc[i][4], acc[i][5], acc[i][6], acc[i][7]);
        *(float4*)&g_WT[row * OUTD + tx * 4]      = w0;
        *(float4*)&g_WT[row * OUTD + 64 + tx * 4] = w1;
    }
}

// ---------------------------------------------------------------------------
// Kernel 2: main gathered GEMM, tf32 wmma, cp.async 3-stage pipeline.
//   C[128x128 tile] += A_gathered[128 x 16384(+128 self)] @ B[... x 128]
//   grid.x = 128: tile = bx & 63 (64 M-tiles), split = bx >> 6 (2 K-splits)
// ---------------------------------------------------------------------------
#define BM 128
#define BN 128
#define BK 32
#define LDA 40        // A stage stride (floats), mult of 8
#define LDB 136       // B stage stride (floats), mult of 8
#define STAGE_F (BM * LDA + BK * LDB)   // 5120 + 4352 = 9472 floats
#define NSTAGE 3
#define SMEM_BYTES (NSTAGE * STAGE_F * 4)   // 113664
#define NKT 512       // k-iterations per split (16384 / 32)

__device__ __forceinline__ void cp_async16(uint32_t dst, const void* src) {
    asm volatile("cp.async.cg.shared.global [%0], [%1], 16;\n"
                 :: "r"(dst), "l"(src));
}
__device__ __forceinline__ void cp_commit() {
    asm volatile("cp.async.commit_group;\n" ::: "memory");
}
__device__ __forceinline__ void cp_wait1() {
    asm volatile("cp.async.wait_group 1;\n" ::: "memory");
}

typedef wmma::fragment<wmma::matrix_a, 16, 16, 8, wmma::precision::tf32, wmma::row_major> FragA;
typedef wmma::fragment<wmma::matrix_b, 16, 16, 8, wmma::precision::tf32, wmma::row_major> FragB;
typedef wmma::fragment<wmma::accumulator, 16, 16, 8, float> FragC;

__global__ __launch_bounds__(256, 1) void main_kernel(
    const float* __restrict__ adj,       // [8,4096,4096]
    const int*   __restrict__ head_idx,  // [4096]
    const int*   __restrict__ tail_idx,  // [4096]
    const float* __restrict__ head_e,    // [4096,128]
    const float* __restrict__ tail_e,    // [4096,128]
    const float* __restrict__ selfK,     // [128,128]
    float*       __restrict__ out)       // [8192,128]
{
    extern __shared__ float smem[];
    __shared__ long long rowoff[BM];     // gather offsets (elements) per A row

    const int tid   = threadIdx.x;
    const int bx    = blockIdx.x;
    const int tile  = bx & 63;
    const int split = bx >> 6;

    const int gm0    = tile * BM;        // 0..8191
    const int branch = tile >> 5;        // 0 head, 1 tail
    const int b0     = (tile & 31) * BM; // 0..3968

    const int*   idxp = branch ? tail_idx : head_idx;
    const float* ep   = branch ? tail_e  : head_e;

    if (tid < BM) {
        rowoff[tid] = (long long)idxp[b0 + tid] * NN;
    }
    __syncthreads();

    const int kbase = split * (RR / 2) * NN;   // 0 or 16384
    const int T = NKT + (split == 0 ? 4 : 0);  // self term folded into split 0

    // Per-thread copy assignments (constant across iterations):
    //  A: 128 rows x 32 floats; thread t -> row t/2, 16-float half (t&1)
    const int a_row = tid >> 1;
    const int a_fo  = (tid & 1) * 16;
    //  B: 32 rows x 128 floats; thread t -> rows (t>>5)+{0,8,16,24}, cols (t&31)*4
    const int b_row = tid >> 5;
    const int b_col = (tid & 31) * 4;

    const uint32_t smem_u32 = (uint32_t)__cvta_generic_to_shared(smem);

    // ---- loader: issue one stage's cp.async (no commit) ----
    auto issue = [&](int it, int s) {
        float* As = smem + s * STAGE_F;
        float* Bs = As + BM * LDA;
        uint32_t a_dst = smem_u32 + (uint32_t)((s * STAGE_F + a_row * LDA + a_fo) * 4);
        uint32_t b_dst = smem_u32 + (uint32_t)((s * STAGE_F + BM * LDA + b_row * LDB + b_col) * 4);
        (void)As; (void)Bs;

        const float* asrc;
        const float* bsrc;
        long long bstep;
        if (it < NKT) {
            int kg = kbase + it * BK;        // global k, 0..32735
            int r  = kg >> 12;               // relation
            int n0 = kg & (NN - 1);
            asrc = adj + ((size_t)r << 24) + (size_t)rowoff[a_row] + n0 + a_fo;
            bsrc = g_WT + (size_t)(kg + b_row) * OUTD + b_col;
            bstep = (long long)8 * OUTD;
        } else {
            int d0 = (it - NKT) * BK;
            asrc = ep + (size_t)(b0 + a_row) * DD + d0 + a_fo;
            bsrc = selfK + (size_t)(d0 + b_row) * OUTD + b_col;
            bstep = (long long)8 * OUTD;
        }
        // A: 4 x 16B (64 contiguous bytes)
#pragma unroll
        for (int c = 0; c < 4; c++)
            cp_async16(a_dst + c * 16, asrc + c * 4);
        // B: 4 rows, 16B each
#pragma unroll
        for (int k = 0; k < 4; k++)
            cp_async16(b_dst + (uint32_t)(k * 8 * LDB * 4), bsrc + k * bstep);
    };

    // warp tiling: 2 x 4 warps, each 64 x 32
    const int wid = tid >> 5;
    const int wm  = (wid >> 2) * 64;   // 0 or 64
    const int wn  = (wid & 3) * 32;    // 0,32,64,96

    FragC acc[4][2];
#pragma unroll
    for (int i = 0; i < 4; i++)
#pragma unroll
        for (int j = 0; j < 2; j++) wmma::fill_fragment(acc[i][j], 0.0f);

    // prologue: stages 0 and 1
    issue(0, 0); cp_commit();
    issue(1, 1); cp_commit();

    for (int it = 0; it < T; it++) {
        const int s = it % NSTAGE;
        cp_wait1();          // group `it` complete (exactly one newer group pending)
        __syncthreads();
        if (it + 2 < T) issue(it + 2, (it + 2) % NSTAGE);
        cp_commit();         // commit every iter (possibly empty) to keep count math valid

        const float* As = smem + s * STAGE_F;
        const float* Bs = As + BM * LDA;
        const float* Aw = As + wm * LDA;
        const float* Bw = Bs + wn;

#pragma unroll
        for (int ks = 0; ks < 4; ks++) {
            FragA af[4];
            FragB bf[2];
#pragma unroll
            for (int i = 0; i < 4; i++) {
                wmma::load_matrix_sync(af[i], Aw + (i * 16) * LDA + ks * 8, LDA);
#pragma unroll
                for (int t = 0; t < af[i].num_elements; t++)
                    af[i].x[t] = wmma::__float_to_tf32(af[i].x[t]);
            }
#pragma unroll
            for (int j = 0; j < 2; j++) {
                wmma::load_matrix_sync(bf[j], Bw + (ks * 8) * LDB + j * 16, LDB);
#pragma unroll
                for (int t = 0; t < bf[j].num_elements; t++)
                    bf[j].x[t] = wmma::__float_to_tf32(bf[j].x[t]);
            }
#pragma unroll
            for (int i = 0; i < 4; i++)
#pragma unroll
                for (int j = 0; j < 2; j++)
                    wmma::mma_sync(acc[i][j], af[i], bf[j], acc[i][j]);
        }
    }

    // ---- epilogue: stage C tile in smem, then coalesced atomicAdd ----
    __syncthreads();                      // everyone done with pipeline smem
    float* Csm = smem;                    // 128 x 136 floats = 69632 B, fits
#pragma unroll
    for (int i = 0; i < 4; i++)
#pragma unroll
        for (int j = 0; j < 2; j++)
            wmma::store_matrix_sync(Csm + (wm + i * 16) * 136 + (wn + j * 16),
                                    acc[i][j], 136, wmma::mem_row_major);
    __syncthreads();

    for (int e = tid; e < BM * BN; e += 256) {
        int row = e >> 7;
        int col = e & 127;
        atomicAdd(&out[(size_t)(gm0 + row) * OUTD + col], Csm[row * 136 + col]);
    }
}

// ---------------------------------------------------------------------------
// Launch
// ---------------------------------------------------------------------------
extern "C" void kernel_launch(void* const* d_in, const int* in_sizes, int n_in,
                              void* d_out, int out_size) {
    const float* emb      = (const float*)d_in[0];
    const int*   head_idx = (const int*)  d_in[1];
    const float* head_e   = (const float*)d_in[2];
    const int*   tail_idx = (const int*)  d_in[3];
    const float* tail_e   = (const float*)d_in[4];
    const float* adj      = (const float*)d_in[5];
    const float* relK     = (const float*)d_in[6];
    const float* selfK    = (const float*)d_in[7];
    float* out = (float*)d_out;

    static bool attr_set = false;
    if (!attr_set) {
        cudaFuncSetAttribute(main_kernel,
                             cudaFuncAttributeMaxDynamicSharedMemorySize,
                             SMEM_BYTES);
        attr_set = true;
    }

    // 1) zero output (poisoned before timing)
    {
        int n = out_size;
        int blocks = (n + 255) / 256;
        zero_kernel<<<blocks, 256>>>(out, n);
    }
    // 2) WT precompute (fp32)
    {
        dim3 grid(NN / 128, RR);
        wt_kernel<<<grid, 256>>>(emb, relK);
    }
    // 3) gathered GEMM (tf32 wmma), 64 M-tiles x 2 K-splits
    {
        main_kernel<<<128, 256, SMEM_BYTES>>>(
            adj, head_idx, tail_idx, head_e, tail_e, selfK, out);
    }
}

// round 9
// speedup vs baseline: 1.0098x; 1.0098x over previous
#include <cuda_runtime.h>
#include <cstdint>
#include <cstddef>
#include <mma.h>

using namespace nvcuda;

// ---------------------------------------------------------------------------
// Problem: N=4096, D=128, R=8, OUT=128, B=4096
//   out[m, o] = e_m . selfK[:,o] + sum_{r,n} adj[r, idx_m, n] * WT[r*4096+n, o]
//   WT[k, o]  = sum_d emb[n,d] * relK[r,d,o],  k = r*4096+n
//   m in [0,8192): m<4096 -> head branch, else tail branch.
// Main gathered GEMM on legacy wmma tf32 (tcgen05 unavailable: harness builds
// through compute_103 PTX where arch-specific instructions are rejected).
// ---------------------------------------------------------------------------

#define NN     4096
#define DD     128
#define RR     8
#define OUTD   128
#define KTOT   (RR * NN)          // 32768
#define NSPLIT 4
#define NKT    (KTOT / NSPLIT / 32)  // 256 iterations of BK=32 per split

// Scratch (device globals — no allocation):
//   g_WT[k][o] : WT, tf32-pre-rounded (16 MB)   (B operand, row=k, col=o)
//   g_SK[d][o] : self_kernel, tf32-pre-rounded
__device__ float g_WT[(size_t)KTOT * OUTD];
__device__ float g_SK[DD * OUTD];

__device__ __forceinline__ float tf32_rn(float x) {
    uint32_t y;
    asm("cvt.rna.tf32.f32 %0, %1;" : "=r"(y) : "f"(x));
    return __uint_as_float(y);
}
__device__ __forceinline__ void cp_async16(uint32_t dst, const void* src) {
    asm volatile("cp.async.cg.shared.global [%0], [%1], 16;\n"
                 :: "r"(dst), "l"(src));
}
__device__ __forceinline__ void cp_commit() {
    asm volatile("cp.async.commit_group;\n" ::: "memory");
}

// ---------------------------------------------------------------------------
// Kernel 0: zero output + pre-round selfK (fused: keeps total launches at 3
// so ncu -s 5 -c 1 captures main_kernel as launch #6)
// ---------------------------------------------------------------------------
__global__ void prep_kernel(float4* __restrict__ out, int n4,
                            const float* __restrict__ selfK) {
    int i = blockIdx.x * blockDim.x + threadIdx.x;
    if (i < n4) out[i] = make_float4(0.f, 0.f, 0.f, 0.f);
    if (i < DD * OUTD) g_SK[i] = tf32_rn(selfK[i]);   // same [d][o] layout
}

// ---------------------------------------------------------------------------
// Kernel 1: WT precompute (fp32 register-tiled GEMM, tf32-rounded store)
//   g_WT[r*4096+n][o] = round_tf32( sum_d emb[n,d] * relK[r,d,o] )
// grid (32 n-tiles, 8 r), 256 threads.
// ---------------------------------------------------------------------------
__global__ __launch_bounds__(256) void wt_kernel(
    const float* __restrict__ emb,     // [4096,128]
    const float* __restrict__ relK)    // [8,128,128]
{
    __shared__ float At[32 * 129];     // transposed A tile [d][n]
    __shared__ float Bsh[32 * 132];    // B tile [d][o]

    const int r   = blockIdx.y;
    const int n0  = blockIdx.x * 128;
    const int tid = threadIdx.x;
    const int ty  = tid >> 4;
    const int tx  = tid & 15;

    const float* B0 = relK + (size_t)r * DD * OUTD;

    float acc[8][8];
#pragma unroll
    for (int i = 0; i < 8; i++)
#pragma unroll
        for (int j = 0; j < 8; j++) acc[i][j] = 0.0f;

    for (int k0 = 0; k0 < DD; k0 += 32) {
        __syncthreads();
#pragma unroll
        for (int e = tid; e < 128 * 32; e += 256) {
            int row = e >> 5, d = e & 31;
            At[d * 129 + row] = emb[(size_t)(n0 + row) * DD + k0 + d];
        }
#pragma unroll
        for (int e = tid; e < 32 * 128; e += 256) {
            int d = e >> 7, o = e & 127;
            Bsh[d * 132 + o] = B0[(size_t)(k0 + d) * OUTD + o];
        }
        __syncthreads();
#pragma unroll
        for (int kk = 0; kk < 32; kk++) {
            float a[8];
#pragma unroll
            for (int i = 0; i < 8; i++) a[i] = At[kk * 129 + ty * 8 + i];
            float4 v0 = *(const float4*)&Bsh[kk * 132 + tx * 4];
            float4 v1 = *(const float4*)&Bsh[kk * 132 + 64 + tx * 4];
            float b[8] = {v0.x, v0.y, v0.z, v0.w, v1.x, v1.y, v1.z, v1.w};
#pragma unroll
            for (int i = 0; i < 8; i++)
#pragma unroll
                for (int j = 0; j < 8; j++)
                    acc[i][j] = fmaf(a[i], b[j], acc[i][j]);
        }
    }

#pragma unroll
    for (int i = 0; i < 8; i++) {
        size_t row = (size_t)r * NN + n0 + ty * 8 + i;
        float4 w0 = make_float4(tf32_rn(acc[i][0]), tf32_rn(acc[i][1]),
                                tf32_rn(acc[i][2]), tf32_rn(acc[i][3]));
        float4 w1 = make_float4(tf32_rn(acc[i][4]), tf32_rn(acc[i][5]),
                                tf32_rn(acc[i][6]), tf32_rn(acc[i][7]));
        *(float4*)&g_WT[row * OUTD + tx * 4]      = w0;
        *(float4*)&g_WT[row * OUTD + 64 + tx * 4] = w1;
    }
}

// ---------------------------------------------------------------------------
// Kernel 2: main gathered GEMM, tf32 wmma, 64x64 warp tiles, 2 CTAs/SM.
//   grid.x = 256: tile = bx & 63 (M-tile of 128 rows), split = bx >> 6 (0..3)
//   BM=128, BN=128, BK=32; 128 threads = 4 warps (2x2 of 64x64).
//   No per-fragment tf32 converts: B pre-rounded; A truncated by HW.
// ---------------------------------------------------------------------------
#define BM 128
#define BN 128
#define BK 32
#define LDA 36                      // A stage row stride (floats), mult of 4
#define LDB 132                     // B stage row stride (floats), mult of 4
#define A_STAGE_F (BM * LDA)        // 4608 floats = 18432 B
#define B_STAGE_F (BK * LDB)        // 4224 floats = 16896 B
#define STAGE_F   (A_STAGE_F + B_STAGE_F)   // 8832 floats = 35328 B
#define NS 3
#define SMEM_MAIN (NS * STAGE_F * 4)        // 105984 B

typedef wmma::fragment<wmma::matrix_a, 16, 16, 8, wmma::precision::tf32, wmma::row_major> FragA;
typedef wmma::fragment<wmma::matrix_b, 16, 16, 8, wmma::precision::tf32, wmma::row_major> FragB;
typedef wmma::fragment<wmma::accumulator, 16, 16, 8, float> FragC;

__global__ __launch_bounds__(128) void main_kernel(
    const float* __restrict__ adj,       // [8,4096,4096]
    const int*   __restrict__ head_idx,
    const int*   __restrict__ tail_idx,
    const float* __restrict__ head_e,    // [4096,128]
    const float* __restrict__ tail_e,
    float*       __restrict__ out)       // [8192,128]
{
    extern __shared__ float smem[];
    __shared__ long long rowoff[BM];

    const int tid   = threadIdx.x;       // 0..127
    const int wid   = tid >> 5;          // 0..3
    const int bx    = blockIdx.x;
    const int tile  = bx & 63;
    const int split = bx >> 6;           // 0..3

    const int gm0    = tile * BM;
    const int branch = tile >> 5;
    const int b0     = (tile & 31) * BM;

    const int*   idxp = branch ? tail_idx : head_idx;
    const float* ep   = branch ? tail_e  : head_e;

    rowoff[tid] = (long long)idxp[b0 + tid] * NN;
    __syncthreads();

    const int kbase = split * (KTOT / NSPLIT);      // 0,8192,16384,24576
    const int T     = NKT + (split == 0 ? 4 : 0);   // self term in split 0

    // loader assignments (128 threads):
    //  A: row = tid (128 rows x 32 floats = 8 x 16B chunks)
    //  B: row = tid>>2 (32 rows), col base = (tid&3)*32, 8 x 16B chunks
    const int brow  = tid >> 2;
    const int bcol0 = (tid & 3) * 32;

    const uint32_t sm32 = (uint32_t)__cvta_generic_to_shared(smem);

    auto issue = [&](int j) {
        const int s = j % NS;
        const uint32_t astage = sm32 + (uint32_t)(s * STAGE_F * 4);
        const uint32_t bstage = astage + A_STAGE_F * 4;
        const float* asrc;
        const float* bsrc;
        if (j < NKT) {
            int kg = kbase + j * BK;
            int r  = kg >> 12;
            int n0 = kg & (NN - 1);
            asrc = adj + ((size_t)r << 24) + (size_t)rowoff[tid] + n0;
            bsrc = g_WT + (size_t)(kg + brow) * OUTD + bcol0;
        } else {
            int d0 = (j - NKT) * BK;
            asrc = ep + (size_t)(b0 + tid) * DD + d0;
            bsrc = g_SK + (size_t)(d0 + brow) * OUTD + bcol0;
        }
        const uint32_t a_dst = astage + (uint32_t)tid * (LDA * 4);
        const uint32_t b_dst = bstage + (uint32_t)brow * (LDB * 4) + (uint32_t)bcol0 * 4;
#pragma unroll
        for (int c = 0; c < 8; c++) {
            cp_async16(a_dst + c * 16, asrc + c * 4);
            cp_async16(b_dst + c * 16, bsrc + c * 4);
        }
    };

    // warp tiling: 2x2 warps of 64x64
    const int wm = (wid >> 1) * 64;
    const int wn = (wid & 1) * 64;

    FragC acc[4][4];
#pragma unroll
    for (int i = 0; i < 4; i++)
#pragma unroll
        for (int j = 0; j < 4; j++) wmma::fill_fragment(acc[i][j], 0.0f);

    // prologue: stages 0,1
    issue(0); cp_commit();
    issue(1); cp_commit();

    for (int it = 0; it < T; it++) {
        const int s = it % NS;
        asm volatile("cp.async.wait_group 1;\n" ::: "memory");
        __syncthreads();
        if (it + 2 < T) issue(it + 2);
        cp_commit();

        const float* As = smem + s * STAGE_F;
        const float* Bs = As + A_STAGE_F;
        const float* Aw = As + wm * LDA;
        const float* Bw = Bs + wn;

#pragma unroll
        for (int ks = 0; ks < 4; ks++) {
            FragA af[4];
            FragB bf[4];
#pragma unroll
            for (int i = 0; i < 4; i++)
                wmma::load_matrix_sync(af[i], Aw + (i * 16) * LDA + ks * 8, LDA);
#pragma unroll
            for (int j = 0; j < 4; j++)
                wmma::load_matrix_sync(bf[j], Bw + (ks * 8) * LDB + j * 16, LDB);
            // no __float_to_tf32: B pre-rounded, A truncated by hardware
#pragma unroll
            for (int i = 0; i < 4; i++)
#pragma unroll
                for (int j = 0; j < 4; j++)
                    wmma::mma_sync(acc[i][j], af[i], bf[j], acc[i][j]);
        }
    }

    // epilogue: stage C in smem (128 x 132), coalesced atomicAdd
    __syncthreads();
    float* Csm = smem;
#pragma unroll
    for (int i = 0; i < 4; i++)
#pragma unroll
        for (int j = 0; j < 4; j++)
            wmma::store_matrix_sync(Csm + (wm + i * 16) * 132 + (wn + j * 16),
                                    acc[i][j], 132, wmma::mem_row_major);
    __syncthreads();

#pragma unroll
    for (int i = 0; i < BM; i++)
        atomicAdd(&out[(size_t)(gm0 + i) * OUTD + tid], Csm[i * 132 + tid]);
}

// ---------------------------------------------------------------------------
// Launch (3 launches per call)
// ---------------------------------------------------------------------------
extern "C" void kernel_launch(void* const* d_in, const int* in_sizes, int n_in,
                              void* d_out, int out_size) {
    const float* emb      = (const float*)d_in[0];
    const int*   head_idx = (const int*)  d_in[1];
    const float* head_e   = (const float*)d_in[2];
    const int*   tail_idx = (const int*)  d_in[3];
    const float* tail_e   = (const float*)d_in[4];
    const float* adj      = (const float*)d_in[5];
    const float* relK     = (const float*)d_in[6];
    const float* selfK    = (const float*)d_in[7];
    float* out = (float*)d_out;

    cudaFuncSetAttribute(main_kernel,
                         cudaFuncAttributeMaxDynamicSharedMemorySize,
                         SMEM_MAIN);

    // 1) zero output + pre-round selfK
    {
        int n4 = out_size / 4;
        prep_kernel<<<(n4 + 255) / 256, 256>>>((float4*)out, n4, selfK);
    }
    // 2) WT precompute (fp32, tf32-rounded store)
    {
        dim3 grid(NN / 128, RR);
        wt_kernel<<<grid, 256>>>(emb, relK);
    }
    // 3) gathered GEMM (tf32 wmma), 64 M-tiles x 4 K-splits, 2 CTAs/SM
    main_kernel<<<256, 128, SMEM_MAIN>>>(adj, head_idx, tail_idx,
                                         head_e, tail_e, out);
}

// round 11
// speedup vs baseline: 1.8232x; 1.8055x over previous
#include <cuda_runtime.h>
#include <cuda_fp16.h>
#include <cstdint>
#include <cstddef>
#include <mma.h>

using namespace nvcuda;

// ---------------------------------------------------------------------------
// Problem: N=4096, D=128, R=8, OUT=128, B=4096
// Reference order (2x fewer FLOPs than the WT restructuring):
//   stage1: upd[br][r][b][d] = sum_n adj[r, idx_b, n] * emb[n, d]   (fp16 wmma)
//   stage2: out[br][b][o]    = sum_{rd} upd * relK[r,d,o] + e . selfK (fp32)
// Legacy wmma only: harness builds through compute_103 PTX (no tcgen05).
// ---------------------------------------------------------------------------

#define NN    4096
#define DD    128
#define RR    8
#define OUTD  128

// Device-global scratch (no allocation):
__device__ __half g_adj_h[(size_t)RR * NN * NN];   // 256 MB, adj in fp16
__device__ __half g_emb_h[NN * DD];                // 1 MB, emb in fp16
__device__ float  g_upd[(size_t)2 * NN * RR * DD]; // 32 MB, [br][b][r*128+d]

__device__ __forceinline__ void cp_async16(uint32_t dst, const void* src) {
    asm volatile("cp.async.cg.shared.global [%0], [%1], 16;\n"
                 :: "r"(dst), "l"(src));
}
__device__ __forceinline__ void cp_commit() {
    asm volatile("cp.async.commit_group;\n" ::: "memory");
}

// ---------------------------------------------------------------------------
// Kernel 0: zero output + convert emb -> fp16
// ---------------------------------------------------------------------------
__global__ void prep_kernel(float4* __restrict__ out, int n4,
                            const float2* __restrict__ emb2) {
    int i = blockIdx.x * blockDim.x + threadIdx.x;
    if (i < n4) out[i] = make_float4(0.f, 0.f, 0.f, 0.f);
    if (i < NN * DD / 2) {
        float2 v = emb2[i];
        ((__half2*)g_emb_h)[i] = __floats2half2_rn(v.x, v.y);
    }
}

// ---------------------------------------------------------------------------
// Kernel 1: convert adj (512 MB fp32) -> g_adj_h (256 MB fp16), streaming
// ---------------------------------------------------------------------------
__global__ void adjconv_kernel(const float4* __restrict__ adj4) {
    size_t i = (size_t)blockIdx.x * blockDim.x + threadIdx.x;  // 33554432
    float4 v = adj4[i];
    __half2 h0 = __floats2half2_rn(v.x, v.y);
    __half2 h1 = __floats2half2_rn(v.z, v.w);
    uint2 w;
    w.x = *(const uint32_t*)&h0;
    w.y = *(const uint32_t*)&h1;
    ((uint2*)g_adj_h)[i] = w;
}

// ---------------------------------------------------------------------------
// Kernel 2: stage1 gathered GEMM, fp16 wmma m16n16k16, fp32 accum.
//   grid.x = 512: tile = bx&31 (128 b-rows), r = (bx>>5)&7, branch = bx>>8
//   C[128x128] = A_gathered[128 x 4096] @ emb_h[4096 x 128]
//   BK=64, 3-stage cp.async, 4 warps (2x2 of 64x64), 2 CTAs/SM.
// ---------------------------------------------------------------------------
#define S1_BK   64
#define S1_LDA  72                      // halves per A row (144 B, 16B-mult)
#define S1_LDB  136                     // halves per B row (272 B, 16B-mult)
#define S1_ASTG (128 * S1_LDA)          // 9216 halves = 18432 B
#define S1_BSTG (S1_BK * S1_LDB)        // 8704 halves = 17408 B
#define S1_STG  (S1_ASTG + S1_BSTG)     // 17920 halves = 35840 B
#define S1_NS   3
#define S1_SMEM (S1_NS * S1_STG * 2)    // 107520 B
#define S1_NIT  (NN / S1_BK)            // 64

typedef wmma::fragment<wmma::matrix_a, 16, 16, 16, __half, wmma::row_major> HFragA;
typedef wmma::fragment<wmma::matrix_b, 16, 16, 16, __half, wmma::row_major> HFragB;
typedef wmma::fragment<wmma::accumulator, 16, 16, 16, float> HFragC;

__global__ __launch_bounds__(128) void stage1_kernel(
    const int* __restrict__ head_idx,
    const int* __restrict__ tail_idx)
{
    extern __shared__ __half smh[];
    __shared__ long long rowoff[128];

    const int tid    = threadIdx.x;       // 0..127
    const int wid    = tid >> 5;
    const int bx     = blockIdx.x;
    const int tile   = bx & 31;
    const int r      = (bx >> 5) & 7;
    const int branch = bx >> 8;

    const int b0 = tile * 128;
    const int* idxp = branch ? tail_idx : head_idx;
    rowoff[tid] = (long long)idxp[b0 + tid] * NN;
    __syncthreads();

    const uint32_t sm32 = (uint32_t)__cvta_generic_to_shared(smh);
    const __half* adjh = g_adj_h + ((size_t)r << 24);

    // loader assignments:
    //  A: row = tid, 8 x 16B chunks (64 halves)
    //  B: brow = tid>>1, half-row = (tid&1)*64 halves, 8 x 16B chunks
    const int brow = tid >> 1;
    const int bh0  = (tid & 1) * 64;

    auto issue = [&](int j) {
        const int s = j % S1_NS;
        const int n0 = j * S1_BK;
        const uint32_t astage = sm32 + (uint32_t)(s * S1_STG * 2);
        const uint32_t bstage = astage + S1_ASTG * 2;
        const __half* asrc = adjh + (size_t)rowoff[tid] + n0;
        const __half* bsrc = g_emb_h + (size_t)(n0 + brow) * DD + bh0;
        const uint32_t a_dst = astage + (uint32_t)tid * (S1_LDA * 2);
        const uint32_t b_dst = bstage + (uint32_t)(brow * S1_LDB + bh0) * 2;
#pragma unroll
        for (int c = 0; c < 8; c++) {
            cp_async16(a_dst + c * 16, asrc + c * 8);
            cp_async16(b_dst + c * 16, bsrc + c * 8);
        }
    };

    const int wm = (wid >> 1) * 64;
    const int wn = (wid & 1) * 64;

    HFragC acc[4][4];
#pragma unroll
    for (int i = 0; i < 4; i++)
#pragma unroll
        for (int j = 0; j < 4; j++) wmma::fill_fragment(acc[i][j], 0.0f);

    issue(0); cp_commit();
    issue(1); cp_commit();

    for (int it = 0; it < S1_NIT; it++) {
        const int s = it % S1_NS;
        asm volatile("cp.async.wait_group 1;\n" ::: "memory");
        __syncthreads();
        if (it + 2 < S1_NIT) issue(it + 2);
        cp_commit();

        const __half* As = smh + s * S1_STG;
        const __half* Bs = As + S1_ASTG;
        const __half* Aw = As + wm * S1_LDA;
        const __half* Bw = Bs + wn;

#pragma unroll
        for (int ks = 0; ks < 4; ks++) {
            HFragA af[4];
            HFragB bf[4];
#pragma unroll
            for (int i = 0; i < 4; i++)
                wmma::load_matrix_sync(af[i], Aw + (i * 16) * S1_LDA + ks * 16, S1_LDA);
#pragma unroll
            for (int j = 0; j < 4; j++)
                wmma::load_matrix_sync(bf[j], Bw + (ks * 16) * S1_LDB + j * 16, S1_LDB);
#pragma unroll
            for (int i = 0; i < 4; i++)
#pragma unroll
                for (int j = 0; j < 4; j++)
                    wmma::mma_sync(acc[i][j], af[i], bf[j], acc[i][j]);
        }
    }

    // epilogue: C[128 b][128 d] -> g_upd[(branch*4096 + b0+row)*1024 + r*128 + d]
    __syncthreads();
    float* Csm = (float*)smh;             // 128 x 132 floats = 67584 B < 107520 ok
#pragma unroll
    for (int i = 0; i < 4; i++)
#pragma unroll
        for (int j = 0; j < 4; j++)
            wmma::store_matrix_sync(Csm + (wm + i * 16) * 132 + (wn + j * 16),
                                    acc[i][j], 132, wmma::mem_row_major);
    __syncthreads();

    const size_t obase = ((size_t)(branch << 12) + b0) * (RR * DD) + (r << 7);
#pragma unroll
    for (int i = 0; i < 128; i++)
        g_upd[obase + (size_t)i * (RR * DD) + tid] = Csm[i * 132 + tid];
}

// ---------------------------------------------------------------------------
// Kernel 3: stage2, exact fp32 tiled GEMM with folded self term.
//   out[m][o] = sum_{k<1024} upd[m][k]*relK_flat[k][o]
//             + sum_{k>=1024} e(m)[k-1024]*selfK[k-1024][o]
//   grid 128 = tile(0..63) | split<<6; K=1152 split 576/576 (self in split 1).
// ---------------------------------------------------------------------------
__global__ __launch_bounds__(256) void stage2_kernel(
    const float* __restrict__ head_e,
    const float* __restrict__ tail_e,
    const float* __restrict__ relK,      // [8*128,128] flat
    const float* __restrict__ selfK,     // [128,128]
    float*       __restrict__ out)       // [8192,128]
{
    __shared__ float At[32 * 129];       // transposed A tile [k][m]
    __shared__ float Bsh[32 * 132];      // B tile [k][o]

    const int bx    = blockIdx.x;
    const int tile  = bx & 63;
    const int split = bx >> 6;
    const int m0    = tile * 128;
    const int tid   = threadIdx.x;
    const int ty    = tid >> 4;
    const int tx    = tid & 15;
    const int kstart = split * 576;

    float acc[8][8];
#pragma unroll
    for (int i = 0; i < 8; i++)
#pragma unroll
        for (int j = 0; j < 8; j++) acc[i][j] = 0.0f;

    for (int w = 0; w < 18; w++) {
        const int k0 = kstart + w * 32;
        __syncthreads();
        // A tile: At[d][row] = A2[m0+row][k0+d]
#pragma unroll
        for (int e = tid; e < 128 * 32; e += 256) {
            int row = e >> 5, d = e & 31;
            int k = k0 + d, m = m0 + row;
            float v;
            if (k < 1024) {
                v = g_upd[(size_t)m * 1024 + k];
            } else {
                int dd = k - 1024;
                v = (m < 4096) ? head_e[(size_t)m * DD + dd]
                               : tail_e[(size_t)(m - 4096) * DD + dd];
            }
            At[d * 129 + row] = v;
        }
        // B tile: Bsh[d][o] = B2[k0+d][o]
#pragma unroll
        for (int e = tid; e < 32 * 128; e += 256) {
            int d = e >> 7, o = e & 127;
            int k = k0 + d;
            Bsh[d * 132 + o] = (k < 1024) ? relK[(size_t)k * OUTD + o]
                                          : selfK[(size_t)(k - 1024) * OUTD + o];
        }
        __syncthreads();
#pragma unroll
        for (int kk = 0; kk < 32; kk++) {
            float a[8];
#pragma unroll
            for (int i = 0; i < 8; i++) a[i] = At[kk * 129 + ty * 8 + i];
            float4 v0 = *(const float4*)&Bsh[kk * 132 + tx * 4];
            float4 v1 = *(const float4*)&Bsh[kk * 132 + 64 + tx * 4];
            float b[8] = {v0.x, v0.y, v0.z, v0.w, v1.x, v1.y, v1.z, v1.w};
#pragma unroll
            for (int i = 0; i < 8; i++)
#pragma unroll
                for (int j = 0; j < 8; j++)
                    acc[i][j] = fmaf(a[i], b[j], acc[i][j]);
        }
    }

    // atomicAdd epilogue (out zeroed in prep; 2 split writers per element)
#pragma unroll
    for (int i = 0; i < 8; i++) {
        size_t row = (size_t)(m0 + ty * 8 + i) * OUTD;
#pragma unroll
        for (int c = 0; c < 4; c++) {
            atomicAdd(&out[row + tx * 4 + c],      acc[i][c]);
            atomicAdd(&out[row + 64 + tx * 4 + c], acc[i][4 + c]);
        }
    }
}

// ---------------------------------------------------------------------------
// Launch (4 launches per call)
// ---------------------------------------------------------------------------
extern "C" void kernel_launch(void* const* d_in, const int* in_sizes, int n_in,
                              void* d_out, int out_size) {
    const float* emb      = (const float*)d_in[0];
    const int*   head_idx = (const int*)  d_in[1];
    const float* head_e   = (const float*)d_in[2];
    const int*   tail_idx = (const int*)  d_in[3];
    const float* tail_e   = (const float*)d_in[4];
    const float* adj      = (const float*)d_in[5];
    const float* relK     = (const float*)d_in[6];
    const float* selfK    = (const float*)d_in[7];
    float* out = (float*)d_out;

    cudaFuncSetAttribute(stage1_kernel,
                         cudaFuncAttributeMaxDynamicSharedMemorySize,
                         S1_SMEM);

    // 1) zero output + emb -> fp16
    {
        int n4 = out_size / 4;                       // 262144
        prep_kernel<<<(n4 + 255) / 256, 256>>>((float4*)out, n4,
                                               (const float2*)emb);
    }
    // 2) adj -> fp16 (134.2M elems, one float4 per thread)
    {
        size_t n4 = (size_t)RR * NN * NN / 4;        // 33554432
        adjconv_kernel<<<(unsigned)(n4 / 256), 256>>>((const float4*)adj);
    }
    // 3) stage1: gathered fp16 GEMM -> g_upd
    stage1_kernel<<<512, 128, S1_SMEM>>>(head_idx, tail_idx);
    // 4) stage2: exact fp32 contraction + self term -> out
    stage2_kernel<<<128, 256>>>(head_e, tail_e, relK, selfK, out);
}

// round 12
// speedup vs baseline: 3.7444x; 2.0538x over previous
#include <cuda_runtime.h>
#include <cuda_fp16.h>
#include <cstdint>
#include <cstddef>
#include <mma.h>

using namespace nvcuda;

// ---------------------------------------------------------------------------
// Problem: N=4096, D=128, R=8, OUT=128, B=4096
// Node-dedup restructuring (half the tensor FLOPs of the gathered form):
//   stage1 (dense):   upd_all[node][r*128+d] = sum_n adj[r,node,n]*emb[n,d]
//   stage2 (gather):  out[m][o] = sum_k A2[m][k]*B2[k][o]
//       A2[m][k<1024]  = upd_all[idx_m][k],  A2[m][1024+dd] = e_m[dd]
//       B2[k<1024][o]  = relK_flat[k][o],    B2[1024+dd][o] = selfK[dd][o]
// Legacy wmma fp16 only (compute_103 PTX: no tcgen05).
// ---------------------------------------------------------------------------

#define NN    4096
#define DD    128
#define RR    8
#define OUTD  128
#define KU    (RR * DD)            // 1024
#define K2    (KU + DD)            // 1152

// Device-global scratch (no allocation):
__device__ __half g_adj_h[(size_t)RR * NN * NN];   // 256 MB
__device__ __half g_emb_h[NN * DD];                // 1 MB
__device__ __half g_upd_h[(size_t)NN * KU];        // 8 MB  [node][r*128+d]
__device__ __half g_eh[(size_t)2 * NN * DD];       // 2 MB  [m][d] (head||tail)
__device__ __half g_Bh[K2 * OUTD];                 // 288 KB [k][o]

__device__ __forceinline__ void cp_async16(uint32_t dst, const void* src) {
    asm volatile("cp.async.cg.shared.global [%0], [%1], 16;\n"
                 :: "r"(dst), "l"(src));
}
__device__ __forceinline__ void cp_commit() {
    asm volatile("cp.async.commit_group;\n" ::: "memory");
}

// ---------------------------------------------------------------------------
// Kernel 0: zero output + convert emb/e/relK/selfK -> fp16
// ---------------------------------------------------------------------------
__global__ void prep_kernel(float4* __restrict__ out,
                            const float2* __restrict__ emb2,
                            const float2* __restrict__ head_e2,
                            const float2* __restrict__ tail_e2,
                            const float2* __restrict__ relK2,
                            const float2* __restrict__ selfK2) {
    int i = blockIdx.x * blockDim.x + threadIdx.x;     // 0..524287
    if (i < 262144) out[i] = make_float4(0.f, 0.f, 0.f, 0.f);
    if (i < NN * DD / 2) {                             // emb: 262144 half2
        float2 v = emb2[i];
        ((__half2*)g_emb_h)[i] = __floats2half2_rn(v.x, v.y);
    }
    if (i < 2 * NN * DD / 2) {                         // e: 524288 half2
        float2 v = (i < NN * DD / 2) ? head_e2[i] : tail_e2[i - NN * DD / 2];
        ((__half2*)g_eh)[i] = __floats2half2_rn(v.x, v.y);
    }
    if (i < K2 * OUTD / 2) {                           // B2: 73728 half2
        float2 v = (i < KU * OUTD / 2) ? relK2[i] : selfK2[i - KU * OUTD / 2];
        ((__half2*)g_Bh)[i] = __floats2half2_rn(v.x, v.y);
    }
}

// ---------------------------------------------------------------------------
// Kernel 1: convert adj (512 MB fp32) -> g_adj_h (256 MB fp16), streaming
// ---------------------------------------------------------------------------
__global__ void adjconv_kernel(const float4* __restrict__ adj4) {
    size_t i = (size_t)blockIdx.x * blockDim.x + threadIdx.x;  // 33554432
    float4 v = adj4[i];
    __half2 h0 = __floats2half2_rn(v.x, v.y);
    __half2 h1 = __floats2half2_rn(v.z, v.w);
    uint2 w;
    w.x = *(const uint32_t*)&h0;
    w.y = *(const uint32_t*)&h1;
    ((uint2*)g_adj_h)[i] = w;
}

// ---------------------------------------------------------------------------
// Shared GEMM tile config (stage1 and stage2 use the same shape machinery):
//   BM=128, BN=128, BK=64 halves; 4 warps (2x2 of 64x64); 3-stage cp.async.
// ---------------------------------------------------------------------------
#define BKH     64
#define LDAH    72                      // halves per A row (144 B)
#define LDBH    136                     // halves per B row (272 B)
#define ASTGH   (128 * LDAH)            // 9216 halves
#define BSTGH   (BKH * LDBH)            // 8704 halves
#define STGH    (ASTGH + BSTGH)         // 17920 halves = 35840 B
#define NSH     3
#define SMEM_T  (NSH * STGH * 2)        // 107520 B

typedef wmma::fragment<wmma::matrix_a, 16, 16, 16, __half, wmma::row_major> HFragA;
typedef wmma::fragment<wmma::matrix_b, 16, 16, 16, __half, wmma::row_major> HFragB;
typedef wmma::fragment<wmma::accumulator, 16, 16, 16, float> HFragC;

// ---------------------------------------------------------------------------
// Kernel 2: stage1 dense GEMM per relation.
//   grid.x = 256: r = bx>>5, tile = bx&31; C[128 nodes][128 d] =
//   adj_h[r][node0..node0+127][:] @ emb_h; epilogue converts to fp16 g_upd_h.
// ---------------------------------------------------------------------------
__global__ __launch_bounds__(128) void stage1_kernel() {
    extern __shared__ __half smh[];

    const int tid  = threadIdx.x;
    const int wid  = tid >> 5;
    const int bx   = blockIdx.x;
    const int r    = bx >> 5;
    const int node0 = (bx & 31) * 128;

    const uint32_t sm32 = (uint32_t)__cvta_generic_to_shared(smh);
    const __half* adjh = g_adj_h + ((size_t)r << 24) + (size_t)(node0 + tid) * NN;

    const int brow = tid >> 1;
    const int bh0  = (tid & 1) * 64;

    auto issue = [&](int j) {
        const int s = j % NSH;
        const int n0 = j * BKH;
        const uint32_t astage = sm32 + (uint32_t)(s * STGH * 2);
        const uint32_t bstage = astage + ASTGH * 2;
        const __half* asrc = adjh + n0;
        const __half* bsrc = g_emb_h + (size_t)(n0 + brow) * DD + bh0;
        const uint32_t a_dst = astage + (uint32_t)tid * (LDAH * 2);
        const uint32_t b_dst = bstage + (uint32_t)(brow * LDBH + bh0) * 2;
#pragma unroll
        for (int c = 0; c < 8; c++) {
            cp_async16(a_dst + c * 16, asrc + c * 8);
            cp_async16(b_dst + c * 16, bsrc + c * 8);
        }
    };

    const int wm = (wid >> 1) * 64;
    const int wn = (wid & 1) * 64;

    HFragC acc[4][4];
#pragma unroll
    for (int i = 0; i < 4; i++)
#pragma unroll
        for (int j = 0; j < 4; j++) wmma::fill_fragment(acc[i][j], 0.0f);

    issue(0); cp_commit();
    issue(1); cp_commit();

    const int NIT = NN / BKH;   // 64
    for (int it = 0; it < NIT; it++) {
        const int s = it % NSH;
        asm volatile("cp.async.wait_group 1;\n" ::: "memory");
        __syncthreads();
        if (it + 2 < NIT) issue(it + 2);
        cp_commit();

        const __half* As = smh + s * STGH;
        const __half* Bs = As + ASTGH;
        const __half* Aw = As + wm * LDAH;
        const __half* Bw = Bs + wn;

#pragma unroll
        for (int ks = 0; ks < 4; ks++) {
            HFragA af[4];
            HFragB bf[4];
#pragma unroll
            for (int i = 0; i < 4; i++)
                wmma::load_matrix_sync(af[i], Aw + (i * 16) * LDAH + ks * 16, LDAH);
#pragma unroll
            for (int j = 0; j < 4; j++)
                wmma::load_matrix_sync(bf[j], Bw + (ks * 16) * LDBH + j * 16, LDBH);
#pragma unroll
            for (int i = 0; i < 4; i++)
#pragma unroll
                for (int j = 0; j < 4; j++)
                    wmma::mma_sync(acc[i][j], af[i], bf[j], acc[i][j]);
        }
    }

    // epilogue: C[128 node][128 d] -> g_upd_h[(node0+i)*1024 + r*128 + tid] fp16
    __syncthreads();
    float* Csm = (float*)smh;            // 128 x 132 floats = 67584 B
#pragma unroll
    for (int i = 0; i < 4; i++)
#pragma unroll
        for (int j = 0; j < 4; j++)
            wmma::store_matrix_sync(Csm + (wm + i * 16) * 132 + (wn + j * 16),
                                    acc[i][j], 132, wmma::mem_row_major);
    __syncthreads();

    const size_t obase = (size_t)node0 * KU + (r << 7) + tid;
#pragma unroll
    for (int i = 0; i < 128; i++)
        g_upd_h[obase + (size_t)i * KU] = __float2half(Csm[i * 132 + tid]);
}

// ---------------------------------------------------------------------------
// Kernel 3: stage2 gathered fp16 GEMM with folded self term.
//   grid.x = 128: tile = bx&63 (m0=tile*128), split = bx>>6 (K 576/576).
// ---------------------------------------------------------------------------
__global__ __launch_bounds__(128) void stage2_kernel(
    const int* __restrict__ head_idx,
    const int* __restrict__ tail_idx,
    float*     __restrict__ out)       // [8192,128]
{
    extern __shared__ __half smh[];
    __shared__ int rowidx[128];

    const int tid   = threadIdx.x;
    const int wid   = tid >> 5;
    const int bx    = blockIdx.x;
    const int tile  = bx & 63;
    const int split = bx >> 6;
    const int m0    = tile * 128;
    const int branch = tile >> 5;
    const int b0    = (tile & 31) * 128;

    const int* idxp = branch ? tail_idx : head_idx;
    rowidx[tid] = idxp[b0 + tid];
    __syncthreads();

    const uint32_t sm32 = (uint32_t)__cvta_generic_to_shared(smh);
    const size_t aoff_u = (size_t)rowidx[tid] * KU;      // upd_h row (halves)
    const size_t aoff_e = (size_t)(m0 + tid) * DD;       // g_eh row

    const int brow = tid >> 1;
    const int bh0  = (tid & 1) * 64;
    const int kstart = split * 576;

    auto issue = [&](int j) {
        const int s = j % NSH;
        const int k0 = kstart + j * BKH;
        const uint32_t astage = sm32 + (uint32_t)(s * STGH * 2);
        const uint32_t bstage = astage + ASTGH * 2;
        const __half* asrc = (k0 < KU) ? (g_upd_h + aoff_u + k0)
                                       : (g_eh + aoff_e + (k0 - KU));
        const __half* bsrc = g_Bh + (size_t)(k0 + brow) * OUTD + bh0;
        const uint32_t a_dst = astage + (uint32_t)tid * (LDAH * 2);
        const uint32_t b_dst = bstage + (uint32_t)(brow * LDBH + bh0) * 2;
#pragma unroll
        for (int c = 0; c < 8; c++) {
            cp_async16(a_dst + c * 16, asrc + c * 8);
            cp_async16(b_dst + c * 16, bsrc + c * 8);
        }
    };

    const int wm = (wid >> 1) * 64;
    const int wn = (wid & 1) * 64;

    HFragC acc[4][4];
#pragma unroll
    for (int i = 0; i < 4; i++)
#pragma unroll
        for (int j = 0; j < 4; j++) wmma::fill_fragment(acc[i][j], 0.0f);

    issue(0); cp_commit();
    issue(1); cp_commit();

    const int NIT = 576 / BKH;   // 9
    for (int it = 0; it < NIT; it++) {
        const int s = it % NSH;
        asm volatile("cp.async.wait_group 1;\n" ::: "memory");
        __syncthreads();
        if (it + 2 < NIT) issue(it + 2);
        cp_commit();

        const __half* As = smh + s * STGH;
        const __half* Bs = As + ASTGH;
        const __half* Aw = As + wm * LDAH;
        const __half* Bw = Bs + wn;

#pragma unroll
        for (int ks = 0; ks < 4; ks++) {
            HFragA af[4];
            HFragB bf[4];
#pragma unroll
            for (int i = 0; i < 4; i++)
                wmma::load_matrix_sync(af[i], Aw + (i * 16) * LDAH + ks * 16, LDAH);
#pragma unroll
            for (int j = 0; j < 4; j++)
                wmma::load_matrix_sync(bf[j], Bw + (ks * 16) * LDBH + j * 16, LDBH);
#pragma unroll
            for (int i = 0; i < 4; i++)
#pragma unroll
                for (int j = 0; j < 4; j++)
                    wmma::mma_sync(acc[i][j], af[i], bf[j], acc[i][j]);
        }
    }

    // epilogue: stage C fp32 in smem, coalesced atomicAdd (out zeroed in prep)
    __syncthreads();
    float* Csm = (float*)smh;
#pragma unroll
    for (int i = 0; i < 4; i++)
#pragma unroll
        for (int j = 0; j < 4; j++)
            wmma::store_matrix_sync(Csm + (wm + i * 16) * 132 + (wn + j * 16),
                                    acc[i][j], 132, wmma::mem_row_major);
    __syncthreads();

#pragma unroll
    for (int i = 0; i < 128; i++)
        atomicAdd(&out[(size_t)(m0 + i) * OUTD + tid], Csm[i * 132 + tid]);
}

// ---------------------------------------------------------------------------
// Launch (4 launches per call)
// ---------------------------------------------------------------------------
extern "C" void kernel_launch(void* const* d_in, const int* in_sizes, int n_in,
                              void* d_out, int out_size) {
    const float* emb      = (const float*)d_in[0];
    const int*   head_idx = (const int*)  d_in[1];
    const float* head_e   = (const float*)d_in[2];
    const int*   tail_idx = (const int*)  d_in[3];
    const float* tail_e   = (const float*)d_in[4];
    const float* adj      = (const float*)d_in[5];
    const float* relK     = (const float*)d_in[6];
    const float* selfK    = (const float*)d_in[7];
    float* out = (float*)d_out;

    cudaFuncSetAttribute(stage1_kernel,
                         cudaFuncAttributeMaxDynamicSharedMemorySize, SMEM_T);
    cudaFuncSetAttribute(stage2_kernel,
                         cudaFuncAttributeMaxDynamicSharedMemorySize, SMEM_T);

    // 1) zero output + convert emb/e/relK/selfK
    prep_kernel<<<2048, 256>>>((float4*)out,
                               (const float2*)emb,
                               (const float2*)head_e,
                               (const float2*)tail_e,
                               (const float2*)relK,
                               (const float2*)selfK);
    // 2) adj -> fp16
    {
        size_t n4 = (size_t)RR * NN * NN / 4;        // 33554432
        adjconv_kernel<<<(unsigned)(n4 / 256), 256>>>((const float4*)adj);
    }
    // 3) stage1: dense per-node GEMM -> g_upd_h (fp16)
    stage1_kernel<<<256, 128, SMEM_T>>>();
    // 4) stage2: gathered fp16 GEMM (+ self term) -> out
    stage2_kernel<<<128, 128, SMEM_T>>>(head_idx, tail_idx, out);
}

// round 13
// speedup vs baseline: 4.4585x; 1.1907x over previous
#include <cuda_runtime.h>
#include <cuda_fp16.h>
#include <cstdint>
#include <cstddef>
#include <mma.h>

using namespace nvcuda;

// ---------------------------------------------------------------------------
// Problem: N=4096, D=128, R=8, OUT=128, B=4096
// Node-dedup restructuring:
//   stage1 (dense, fused cvt): upd_all[node][r*128+d] = sum_n adj[r,node,n]*emb[n,d]
//       A = adj fp32 read directly (cp.async), converted fp32->fp16 in-kernel.
//   stage2 (gather):  out[m][o] = sum_k A2[m][k]*B2[k][o]
//       A2[m][k<1024]  = upd_all[idx_m][k],  A2[m][1024+dd] = e_m[dd]
//       B2[k<1024][o]  = relK_flat[k][o],    B2[1024+dd][o] = selfK[dd][o]
// Legacy wmma fp16 only (compute_103 PTX: no tcgen05).
// ---------------------------------------------------------------------------

#define NN    4096
#define DD    128
#define RR    8
#define OUTD  128
#define KU    (RR * DD)            // 1024
#define K2    (KU + DD)            // 1152

// Device-global scratch (no allocation):
__device__ __half g_emb_h[NN * DD];                // 1 MB
__device__ __half g_upd_h[(size_t)NN * KU];        // 8 MB  [node][r*128+d]
__device__ __half g_eh[(size_t)2 * NN * DD];       // 2 MB  [m][d] (head||tail)
__device__ __half g_Bh[K2 * OUTD];                 // 288 KB [k][o]

__device__ __forceinline__ void cp_async16(uint32_t dst, const void* src) {
    asm volatile("cp.async.cg.shared.global [%0], [%1], 16;\n"
                 :: "r"(dst), "l"(src));
}
__device__ __forceinline__ void cp_commit() {
    asm volatile("cp.async.commit_group;\n" ::: "memory");
}

// ---------------------------------------------------------------------------
// Kernel 0: zero output + convert emb/e/relK/selfK -> fp16
// ---------------------------------------------------------------------------
__global__ void prep_kernel(float4* __restrict__ out,
                            const float2* __restrict__ emb2,
                            const float2* __restrict__ head_e2,
                            const float2* __restrict__ tail_e2,
                            const float2* __restrict__ relK2,
                            const float2* __restrict__ selfK2) {
    int i = blockIdx.x * blockDim.x + threadIdx.x;     // 0..524287
    if (i < 262144) out[i] = make_float4(0.f, 0.f, 0.f, 0.f);
    if (i < NN * DD / 2) {                             // emb
        float2 v = emb2[i];
        ((__half2*)g_emb_h)[i] = __floats2half2_rn(v.x, v.y);
    }
    if (i < 2 * NN * DD / 2) {                         // e (head||tail)
        float2 v = (i < NN * DD / 2) ? head_e2[i] : tail_e2[i - NN * DD / 2];
        ((__half2*)g_eh)[i] = __floats2half2_rn(v.x, v.y);
    }
    if (i < K2 * OUTD / 2) {                           // B2 (relK||selfK)
        float2 v = (i < KU * OUTD / 2) ? relK2[i] : selfK2[i - KU * OUTD / 2];
        ((__half2*)g_Bh)[i] = __floats2half2_rn(v.x, v.y);
    }
}

// ---------------------------------------------------------------------------
// wmma fragment types
// ---------------------------------------------------------------------------
typedef wmma::fragment<wmma::matrix_a, 16, 16, 16, __half, wmma::row_major> HFragA;
typedef wmma::fragment<wmma::matrix_b, 16, 16, 16, __half, wmma::row_major> HFragB;
typedef wmma::fragment<wmma::accumulator, 16, 16, 16, float> HFragC;

// ---------------------------------------------------------------------------
// Kernel 1: stage1 dense GEMM per relation with FUSED fp32->fp16 A conversion.
//   grid.x = 256: r = bx>>5, node0 = (bx&31)*128.
//   C[128 nodes][128 d] = adj[r][node0..+127][:] @ emb_h
//   BK=32: A fp32 cp.async (3 stages) -> convert -> Ah fp16 (2 buffers);
//   B fp16 cp.async (3 stages). 4 warps (2x2 of 64x64), 2 CTAs/SM.
// SMEM layout (bytes):
//   [0, 55296)        A32 stages: 3 x 128 rows x 36 floats (18432 B)
//   [55296, 75776)    Ah double buffer: 2 x 128 rows x 40 halves (10240 B)
//   [75776, 101888)   B16 stages: 3 x 32 rows x 136 halves (8704 B)
// ---------------------------------------------------------------------------
#define S1_BK     32
#define A32_LD    36                    // floats per A32 row (144 B)
#define A32_STG_B 18432
#define AH_LD     40                    // halves per Ah row (80 B)
#define AH_STG_B  10240
#define B16_LD    136                   // halves per B16 row (272 B)
#define B16_STG_B 8704
#define OFF_A32   0
#define OFF_AH    55296
#define OFF_B16   75776
#define SMEM_S1   101888
#define S1_NIT    (NN / S1_BK)          // 128

__global__ __launch_bounds__(128) void stage1_kernel(
    const float* __restrict__ adj)       // [8,4096,4096] fp32
{
    extern __shared__ char smc[];

    const int tid   = threadIdx.x;
    const int wid   = tid >> 5;
    const int bx    = blockIdx.x;
    const int r     = bx >> 5;
    const int node0 = (bx & 31) * 128;

    const uint32_t sm32 = (uint32_t)__cvta_generic_to_shared(smc);
    const float* adjrow = adj + ((size_t)r << 24) + (size_t)(node0 + tid) * NN;

    // B loader: 32 rows x 128 halves; 4 threads/row, 32 halves (64 B) each
    const int brow = tid >> 2;
    const int bh0  = (tid & 3) * 32;

    auto issue = [&](int j) {
        const int s = j % 3;
        const int n0 = j * S1_BK;
        // A fp32: row = tid, 32 floats = 8 x 16B
        const uint32_t a_dst = sm32 + OFF_A32 + (uint32_t)s * A32_STG_B
                             + (uint32_t)tid * (A32_LD * 4);
        const float* asrc = adjrow + n0;
#pragma unroll
        for (int c = 0; c < 8; c++)
            cp_async16(a_dst + c * 16, asrc + c * 4);
        // B fp16: 32 halves = 4 x 16B
        const uint32_t b_dst = sm32 + OFF_B16 + (uint32_t)s * B16_STG_B
                             + (uint32_t)(brow * B16_LD + bh0) * 2;
        const __half* bsrc = g_emb_h + (size_t)(n0 + brow) * DD + bh0;
#pragma unroll
        for (int c = 0; c < 4; c++)
            cp_async16(b_dst + c * 16, bsrc + c * 8);
    };

    const int wm = (wid >> 1) * 64;
    const int wn = (wid & 1) * 64;

    HFragC acc[4][4];
#pragma unroll
    for (int i = 0; i < 4; i++)
#pragma unroll
        for (int j = 0; j < 4; j++) wmma::fill_fragment(acc[i][j], 0.0f);

    issue(0); cp_commit();
    issue(1); cp_commit();

    for (int it = 0; it < S1_NIT; it++) {
        const int s = it % 3;
        asm volatile("cp.async.wait_group 1;\n" ::: "memory");
        __syncthreads();

        // convert A32 stage s (row = tid, 32 floats) -> Ah[it&1] fp16
        {
            const float* src = (const float*)(smc + OFF_A32 + s * A32_STG_B)
                             + tid * A32_LD;
            __half* dst = (__half*)(smc + OFF_AH + (it & 1) * AH_STG_B)
                        + tid * AH_LD;
#pragma unroll
            for (int q = 0; q < 8; q++) {
                float4 v = *(const float4*)(src + q * 4);
                __half2 h0 = __floats2half2_rn(v.x, v.y);
                __half2 h1 = __floats2half2_rn(v.z, v.w);
                uint2 w;
                w.x = *(const uint32_t*)&h0;
                w.y = *(const uint32_t*)&h1;
                *(uint2*)(dst + q * 4) = w;
            }
        }
        if (it + 2 < S1_NIT) issue(it + 2);
        cp_commit();
        __syncthreads();

        const __half* Aw = (const __half*)(smc + OFF_AH + (it & 1) * AH_STG_B)
                         + wm * AH_LD;
        const __half* Bw = (const __half*)(smc + OFF_B16 + s * B16_STG_B) + wn;

#pragma unroll
        for (int ks = 0; ks < 2; ks++) {
            HFragA af[4];
            HFragB bf[4];
#pragma unroll
            for (int i = 0; i < 4; i++)
                wmma::load_matrix_sync(af[i], Aw + (i * 16) * AH_LD + ks * 16, AH_LD);
#pragma unroll
            for (int j = 0; j < 4; j++)
                wmma::load_matrix_sync(bf[j], Bw + (ks * 16) * B16_LD + j * 16, B16_LD);
#pragma unroll
            for (int i = 0; i < 4; i++)
#pragma unroll
                for (int j = 0; j < 4; j++)
                    wmma::mma_sync(acc[i][j], af[i], bf[j], acc[i][j]);
        }
    }

    // epilogue: C[128 node][128 d] -> g_upd_h[(node0+i)*1024 + r*128 + tid] fp16
    __syncthreads();
    float* Csm = (float*)smc;            // 128 x 132 floats = 67584 B < SMEM_S1
#pragma unroll
    for (int i = 0; i < 4; i++)
#pragma unroll
        for (int j = 0; j < 4; j++)
            wmma::store_matrix_sync(Csm + (wm + i * 16) * 132 + (wn + j * 16),
                                    acc[i][j], 132, wmma::mem_row_major);
    __syncthreads();

    const size_t obase = (size_t)node0 * KU + (r << 7) + tid;
#pragma unroll
    for (int i = 0; i < 128; i++)
        g_upd_h[obase + (size_t)i * KU] = __float2half(Csm[i * 132 + tid]);
}

// ---------------------------------------------------------------------------
// Kernel 2: stage2 gathered fp16 GEMM with folded self term (as R12, 23 us).
//   grid.x = 128: tile = bx&63 (m0=tile*128), split = bx>>6 (K 576/576).
//   BK=64; 3-stage cp.async; 4 warps (2x2 of 64x64).
// ---------------------------------------------------------------------------
#define BKH     64
#define LDAH    72                      // halves per A row (144 B)
#define LDBH    136                     // halves per B row (272 B)
#define ASTGH   (128 * LDAH)            // 9216 halves
#define BSTGH   (BKH * LDBH)            // 8704 halves
#define STGH    (ASTGH + BSTGH)         // 17920 halves = 35840 B
#define SMEM_T  (3 * STGH * 2)          // 107520 B

__global__ __launch_bounds__(128) void stage2_kernel(
    const int* __restrict__ head_idx,
    const int* __restrict__ tail_idx,
    float*     __restrict__ out)       // [8192,128]
{
    extern __shared__ __half smh[];
    __shared__ int rowidx[128];

    const int tid   = threadIdx.x;
    const int wid   = tid >> 5;
    const int bx    = blockIdx.x;
    const int tile  = bx & 63;
    const int split = bx >> 6;
    const int m0    = tile * 128;
    const int branch = tile >> 5;
    const int b0    = (tile & 31) * 128;

    const int* idxp = branch ? tail_idx : head_idx;
    rowidx[tid] = idxp[b0 + tid];
    __syncthreads();

    const uint32_t sm32 = (uint32_t)__cvta_generic_to_shared(smh);
    const size_t aoff_u = (size_t)rowidx[tid] * KU;
    const size_t aoff_e = (size_t)(m0 + tid) * DD;

    const int brow = tid >> 1;
    const int bh0  = (tid & 1) * 64;
    const int kstart = split * 576;

    auto issue = [&](int j) {
        const int s = j % 3;
        const int k0 = kstart + j * BKH;
        const uint32_t astage = sm32 + (uint32_t)(s * STGH * 2);
        const uint32_t bstage = astage + ASTGH * 2;
        const __half* asrc = (k0 < KU) ? (g_upd_h + aoff_u + k0)
                                       : (g_eh + aoff_e + (k0 - KU));
        const __half* bsrc = g_Bh + (size_t)(k0 + brow) * OUTD + bh0;
        const uint32_t a_dst = astage + (uint32_t)tid * (LDAH * 2);
        const uint32_t b_dst = bstage + (uint32_t)(brow * LDBH + bh0) * 2;
#pragma unroll
        for (int c = 0; c < 8; c++) {
            cp_async16(a_dst + c * 16, asrc + c * 8);
            cp_async16(b_dst + c * 16, bsrc + c * 8);
        }
    };

    const int wm = (wid >> 1) * 64;
    const int wn = (wid & 1) * 64;

    HFragC acc[4][4];
#pragma unroll
    for (int i = 0; i < 4; i++)
#pragma unroll
        for (int j = 0; j < 4; j++) wmma::fill_fragment(acc[i][j], 0.0f);

    issue(0); cp_commit();
    issue(1); cp_commit();

    const int NIT = 576 / BKH;   // 9
    for (int it = 0; it < NIT; it++) {
        const int s = it % 3;
        asm volatile("cp.async.wait_group 1;\n" ::: "memory");
        __syncthreads();
        if (it + 2 < NIT) issue(it + 2);
        cp_commit();

        const __half* As = smh + s * STGH;
        const __half* Bs = As + ASTGH;
        const __half* Aw = As + wm * LDAH;
        const __half* Bw = Bs + wn;

#pragma unroll
        for (int ks = 0; ks < 4; ks++) {
            HFragA af[4];
            HFragB bf[4];
#pragma unroll
            for (int i = 0; i < 4; i++)
                wmma::load_matrix_sync(af[i], Aw + (i * 16) * LDAH + ks * 16, LDAH);
#pragma unroll
            for (int j = 0; j < 4; j++)
                wmma::load_matrix_sync(bf[j], Bw + (ks * 16) * LDBH + j * 16, LDBH);
#pragma unroll
            for (int i = 0; i < 4; i++)
#pragma unroll
                for (int j = 0; j < 4; j++)
                    wmma::mma_sync(acc[i][j], af[i], bf[j], acc[i][j]);
        }
    }

    // epilogue: stage C fp32 in smem, coalesced atomicAdd (out zeroed in prep)
    __syncthreads();
    float* Csm = (float*)smh;
#pragma unroll
    for (int i = 0; i < 4; i++)
#pragma unroll
        for (int j = 0; j < 4; j++)
            wmma::store_matrix_sync(Csm + (wm + i * 16) * 132 + (wn + j * 16),
                                    acc[i][j], 132, wmma::mem_row_major);
    __syncthreads();

#pragma unroll
    for (int i = 0; i < 128; i++)
        atomicAdd(&out[(size_t)(m0 + i) * OUTD + tid], Csm[i * 132 + tid]);
}

// ---------------------------------------------------------------------------
// Launch (3 launches per call)
// ---------------------------------------------------------------------------
extern "C" void kernel_launch(void* const* d_in, const int* in_sizes, int n_in,
                              void* d_out, int out_size) {
    const float* emb      = (const float*)d_in[0];
    const int*   head_idx = (const int*)  d_in[1];
    const float* head_e   = (const float*)d_in[2];
    const int*   tail_idx = (const int*)  d_in[3];
    const float* tail_e   = (const float*)d_in[4];
    const float* adj      = (const float*)d_in[5];
    const float* relK     = (const float*)d_in[6];
    const float* selfK    = (const float*)d_in[7];
    float* out = (float*)d_out;

    cudaFuncSetAttribute(stage1_kernel,
                         cudaFuncAttributeMaxDynamicSharedMemorySize, SMEM_S1);
    cudaFuncSetAttribute(stage2_kernel,
                         cudaFuncAttributeMaxDynamicSharedMemorySize, SMEM_T);

    // 1) zero output + convert emb/e/relK/selfK
    prep_kernel<<<2048, 256>>>((float4*)out,
                               (const float2*)emb,
                               (const float2*)head_e,
                               (const float2*)tail_e,
                               (const float2*)relK,
                               (const float2*)selfK);
    // 2) stage1: dense per-node GEMM, fused fp32->fp16 A conversion
    stage1_kernel<<<256, 128, SMEM_S1>>>(adj);
    // 3) stage2: gathered fp16 GEMM (+ self term) -> out
    stage2_kernel<<<128, 128, SMEM_T>>>(head_idx, tail_idx, out);
}

// round 14
// speedup vs baseline: 5.9000x; 1.3233x over previous
#include <cuda_runtime.h>
#include <cuda_fp16.h>
#include <cstdint>
#include <cstddef>
#include <mma.h>

using namespace nvcuda;

// ---------------------------------------------------------------------------
// Problem: N=4096, D=128, R=8, OUT=128, B=4096
// Node-dedup restructuring:
//   stage1 (dense, reg-fused cvt): upd_all[node][r*128+d] = sum_n adj[r,node,n]*emb[n,d]
//       A = adj fp32 via LDG.128 -> register fp32->fp16 convert -> STS fp16.
//   stage2 (gather):  out[m][o] = sum_k A2[m][k]*B2[k][o]
//       A2[m][k<1024]  = upd_all[idx_m][k],  A2[m][1024+dd] = e_m[dd]
//       B2[k<1024][o]  = relK_flat[k][o],    B2[1024+dd][o] = selfK[dd][o]
// Legacy wmma fp16 only (compute_103 PTX: no tcgen05).
// ---------------------------------------------------------------------------

#define NN    4096
#define DD    128
#define RR    8
#define OUTD  128
#define KU    (RR * DD)            // 1024
#define K2    (KU + DD)            // 1152

// Device-global scratch (no allocation):
__device__ __half g_emb_h[NN * DD];                // 1 MB
__device__ __half g_upd_h[(size_t)NN * KU];        // 8 MB  [node][r*128+d]
__device__ __half g_eh[(size_t)2 * NN * DD];       // 2 MB  [m][d] (head||tail)
__device__ __half g_Bh[K2 * OUTD];                 // 288 KB [k][o]

__device__ __forceinline__ void cp_async16(uint32_t dst, const void* src) {
    asm volatile("cp.async.cg.shared.global [%0], [%1], 16;\n"
                 :: "r"(dst), "l"(src));
}
__device__ __forceinline__ void cp_commit() {
    asm volatile("cp.async.commit_group;\n" ::: "memory");
}

// ---------------------------------------------------------------------------
// Kernel 0: zero output + convert emb/e/relK/selfK -> fp16
// ---------------------------------------------------------------------------
__global__ void prep_kernel(float4* __restrict__ out,
                            const float2* __restrict__ emb2,
                            const float2* __restrict__ head_e2,
                            const float2* __restrict__ tail_e2,
                            const float2* __restrict__ relK2,
                            const float2* __restrict__ selfK2) {
    int i = blockIdx.x * blockDim.x + threadIdx.x;     // 0..524287
    if (i < 262144) out[i] = make_float4(0.f, 0.f, 0.f, 0.f);
    if (i < NN * DD / 2) {                             // emb
        float2 v = emb2[i];
        ((__half2*)g_emb_h)[i] = __floats2half2_rn(v.x, v.y);
    }
    if (i < 2 * NN * DD / 2) {                         // e (head||tail)
        float2 v = (i < NN * DD / 2) ? head_e2[i] : tail_e2[i - NN * DD / 2];
        ((__half2*)g_eh)[i] = __floats2half2_rn(v.x, v.y);
    }
    if (i < K2 * OUTD / 2) {                           // B2 (relK||selfK)
        float2 v = (i < KU * OUTD / 2) ? relK2[i] : selfK2[i - KU * OUTD / 2];
        ((__half2*)g_Bh)[i] = __floats2half2_rn(v.x, v.y);
    }
}

// ---------------------------------------------------------------------------
// wmma fragment types
// ---------------------------------------------------------------------------
typedef wmma::fragment<wmma::matrix_a, 16, 16, 16, __half, wmma::row_major> HFragA;
typedef wmma::fragment<wmma::matrix_b, 16, 16, 16, __half, wmma::row_major> HFragB;
typedef wmma::fragment<wmma::accumulator, 16, 16, 16, float> HFragC;

// ---------------------------------------------------------------------------
// Kernel 1: stage1 dense GEMM per relation, register-fused A conversion.
//   grid.x = 256: r = bx>>5, node0 = (bx&31)*128.
//   C[128 nodes][128 d] = adj[r][node0..+127][:] @ emb_h
//   BK=32. A: LDG.128 x8 (1-iter register prefetch) -> cvt -> STS fp16 into
//   double-buffered Ah. B: emb fp16 via 3-stage cp.async.
//   ONE __syncthreads per iteration (B-issue placed after the sync so stage
//   (it+2)%3 == (it-1)%3 is only overwritten once all warps left wmma_{it-1}).
// SMEM (bytes): Ah 2 x 128 x 40 halves [0,20480) ; B16 3 x 32 x 136 halves
// [20480,46592). Epilogue reuses smem as 128x132 fp32 (67584 B = alloc size).
// ---------------------------------------------------------------------------
#define AH_LD     40                    // halves per Ah row (80 B)
#define AH_STG_B  10240
#define B16_LD    136                   // halves per B16 row (272 B)
#define B16_STG_B 8704
#define OFF_AH    0
#define OFF_B16   20480
#define SMEM_S1   (128 * 132 * 4)       // 67584 (epilogue dominates)
#define S1_NIT    (NN / 32)             // 128

__global__ __launch_bounds__(128, 2) void stage1_kernel(
    const float* __restrict__ adj)       // [8,4096,4096] fp32
{
    extern __shared__ char smc[];

    const int tid   = threadIdx.x;
    const int wid   = tid >> 5;
    const int bx    = blockIdx.x;
    const int r     = bx >> 5;
    const int node0 = (bx & 31) * 128;

    const uint32_t sm32 = (uint32_t)__cvta_generic_to_shared(smc);
    const float* adjrow = adj + ((size_t)r << 24) + (size_t)(node0 + tid) * NN;

    // B loader: 32 rows x 128 halves; 4 threads/row, 32 halves (64 B) each
    const int brow = tid >> 2;
    const int bh0  = (tid & 3) * 32;

    auto issueB = [&](int j) {
        const int s = j % 3;
        const int n0 = j * 32;
        const uint32_t b_dst = sm32 + OFF_B16 + (uint32_t)s * B16_STG_B
                             + (uint32_t)(brow * B16_LD + bh0) * 2;
        const __half* bsrc = g_emb_h + (size_t)(n0 + brow) * DD + bh0;
#pragma unroll
        for (int c = 0; c < 4; c++)
            cp_async16(b_dst + c * 16, bsrc + c * 8);
    };

    const int wm = (wid >> 1) * 64;
    const int wn = (wid & 1) * 64;

    HFragC acc[4][4];
#pragma unroll
    for (int i = 0; i < 4; i++)
#pragma unroll
        for (int j = 0; j < 4; j++) wmma::fill_fragment(acc[i][j], 0.0f);

    // prologue: A regs for iter 0; B stages 0,1
    float4 abuf[8];
#pragma unroll
    for (int q = 0; q < 8; q++) abuf[q] = *(const float4*)(adjrow + q * 4);
    issueB(0); cp_commit();
    issueB(1); cp_commit();

    for (int it = 0; it < S1_NIT; it++) {
        const int s = it % 3;
        asm volatile("cp.async.wait_group 1;\n" ::: "memory");   // B(it) arrived

        // convert abuf (A row tid, iter it) -> Ah[it&1], 32 halves = 4 x STS.128
        {
            __half* dst = (__half*)(smc + OFF_AH + (it & 1) * AH_STG_B)
                        + tid * AH_LD;
#pragma unroll
            for (int q = 0; q < 4; q++) {
                float4 v0 = abuf[2 * q];
                float4 v1 = abuf[2 * q + 1];
                __half2 h0 = __floats2half2_rn(v0.x, v0.y);
                __half2 h1 = __floats2half2_rn(v0.z, v0.w);
                __half2 h2 = __floats2half2_rn(v1.x, v1.y);
                __half2 h3 = __floats2half2_rn(v1.z, v1.w);
                uint4 w;
                w.x = *(const uint32_t*)&h0;
                w.y = *(const uint32_t*)&h1;
                w.z = *(const uint32_t*)&h2;
                w.w = *(const uint32_t*)&h3;
                *(uint4*)(dst + q * 8) = w;
            }
        }
        // register prefetch A for iter it+1 (hides ~600cyc under ~3000cyc body)
        if (it + 1 < S1_NIT) {
            const float* src = adjrow + (it + 1) * 32;
#pragma unroll
            for (int q = 0; q < 8; q++) abuf[q] = *(const float4*)(src + q * 4);
        }

        __syncthreads();   // publishes Ah[it&1] STS + B stage s; closes wmma_{it-1}

        if (it + 2 < S1_NIT) issueB(it + 2);   // safe: all warps past wmma_{it-1}
        cp_commit();                            // commit every iter (count math)

        const __half* Aw = (const __half*)(smc + OFF_AH + (it & 1) * AH_STG_B)
                         + wm * AH_LD;
        const __half* Bw = (const __half*)(smc + OFF_B16 + s * B16_STG_B) + wn;

#pragma unroll
        for (int ks = 0; ks < 2; ks++) {
            HFragA af[4];
            HFragB bf[4];
#pragma unroll
            for (int i = 0; i < 4; i++)
                wmma::load_matrix_sync(af[i], Aw + (i * 16) * AH_LD + ks * 16, AH_LD);
#pragma unroll
            for (int j = 0; j < 4; j++)
                wmma::load_matrix_sync(bf[j], Bw + (ks * 16) * B16_LD + j * 16, B16_LD);
#pragma unroll
            for (int i = 0; i < 4; i++)
#pragma unroll
                for (int j = 0; j < 4; j++)
                    wmma::mma_sync(acc[i][j], af[i], bf[j], acc[i][j]);
        }
    }

    // epilogue: C[128 node][128 d] -> g_upd_h[(node0+i)*1024 + r*128 + tid] fp16
    __syncthreads();
    float* Csm = (float*)smc;            // 128 x 132 floats = 67584 B
#pragma unroll
    for (int i = 0; i < 4; i++)
#pragma unroll
        for (int j = 0; j < 4; j++)
            wmma::store_matrix_sync(Csm + (wm + i * 16) * 132 + (wn + j * 16),
                                    acc[i][j], 132, wmma::mem_row_major);
    __syncthreads();

    const size_t obase = (size_t)node0 * KU + (r << 7) + tid;
#pragma unroll
    for (int i = 0; i < 128; i++)
        g_upd_h[obase + (size_t)i * KU] = __float2half(Csm[i * 132 + tid]);
}

// ---------------------------------------------------------------------------
// Kernel 2: stage2 gathered fp16 GEMM with folded self term (measured 23 us).
//   grid.x = 128: tile = bx&63 (m0=tile*128), split = bx>>6 (K 576/576).
// ---------------------------------------------------------------------------
#define BKH     64
#define LDAH    72                      // halves per A row (144 B)
#define LDBH    136                     // halves per B row (272 B)
#define ASTGH   (128 * LDAH)            // 9216 halves
#define BSTGH   (BKH * LDBH)            // 8704 halves
#define STGH    (ASTGH + BSTGH)         // 17920 halves = 35840 B
#define SMEM_T  (3 * STGH * 2)          // 107520 B

__global__ __launch_bounds__(128) void stage2_kernel(
    const int* __restrict__ head_idx,
    const int* __restrict__ tail_idx,
    float*     __restrict__ out)       // [8192,128]
{
    extern __shared__ __half smh[];
    __shared__ int rowidx[128];

    const int tid   = threadIdx.x;
    const int wid   = tid >> 5;
    const int bx    = blockIdx.x;
    const int tile  = bx & 63;
    const int split = bx >> 6;
    const int m0    = tile * 128;
    const int branch = tile >> 5;
    const int b0    = (tile & 31) * 128;

    const int* idxp = branch ? tail_idx : head_idx;
    rowidx[tid] = idxp[b0 + tid];
    __syncthreads();

    const uint32_t sm32 = (uint32_t)__cvta_generic_to_shared(smh);
    const size_t aoff_u = (size_t)rowidx[tid] * KU;
    const size_t aoff_e = (size_t)(m0 + tid) * DD;

    const int brow = tid >> 1;
    const int bh0  = (tid & 1) * 64;
    const int kstart = split * 576;

    auto issue = [&](int j) {
        const int s = j % 3;
        const int k0 = kstart + j * BKH;
        const uint32_t astage = sm32 + (uint32_t)(s * STGH * 2);
        const uint32_t bstage = astage + ASTGH * 2;
        const __half* asrc = (k0 < KU) ? (g_upd_h + aoff_u + k0)
                                       : (g_eh + aoff_e + (k0 - KU));
        const __half* bsrc = g_Bh + (size_t)(k0 + brow) * OUTD + bh0;
        const uint32_t a_dst = astage + (uint32_t)tid * (LDAH * 2);
        const uint32_t b_dst = bstage + (uint32_t)(brow * LDBH + bh0) * 2;
#pragma unroll
        for (int c = 0; c < 8; c++) {
            cp_async16(a_dst + c * 16, asrc + c * 8);
            cp_async16(b_dst + c * 16, bsrc + c * 8);
        }
    };

    const int wm = (wid >> 1) * 64;
    const int wn = (wid & 1) * 64;

    HFragC acc[4][4];
#pragma unroll
    for (int i = 0; i < 4; i++)
#pragma unroll
        for (int j = 0; j < 4; j++) wmma::fill_fragment(acc[i][j], 0.0f);

    issue(0); cp_commit();
    issue(1); cp_commit();

    const int NIT = 576 / BKH;   // 9
    for (int it = 0; it < NIT; it++) {
        const int s = it % 3;
        asm volatile("cp.async.wait_group 1;\n" ::: "memory");
        __syncthreads();
        if (it + 2 < NIT) issue(it + 2);
        cp_commit();

        const __half* As = smh + s * STGH;
        const __half* Bs = As + ASTGH;
        const __half* Aw = As + wm * LDAH;
        const __half* Bw = Bs + wn;

#pragma unroll
        for (int ks = 0; ks < 4; ks++) {
            HFragA af[4];
            HFragB bf[4];
#pragma unroll
            for (int i = 0; i < 4; i++)
                wmma::load_matrix_sync(af[i], Aw + (i * 16) * LDAH + ks * 16, LDAH);
#pragma unroll
            for (int j = 0; j < 4; j++)
                wmma::load_matrix_sync(bf[j], Bw + (ks * 16) * LDBH + j * 16, LDBH);
#pragma unroll
            for (int i = 0; i < 4; i++)
#pragma unroll
                for (int j = 0; j < 4; j++)
                    wmma::mma_sync(acc[i][j], af[i], bf[j], acc[i][j]);
        }
    }

    // epilogue: stage C fp32 in smem, coalesced atomicAdd (out zeroed in prep)
    __syncthreads();
    float* Csm = (float*)smh;
#pragma unroll
    for (int i = 0; i < 4; i++)
#pragma unroll
        for (int j = 0; j < 4; j++)
            wmma::store_matrix_sync(Csm + (wm + i * 16) * 132 + (wn + j * 16),
                                    acc[i][j], 132, wmma::mem_row_major);
    __syncthreads();

#pragma unroll
    for (int i = 0; i < 128; i++)
        atomicAdd(&out[(size_t)(m0 + i) * OUTD + tid], Csm[i * 132 + tid]);
}

// ---------------------------------------------------------------------------
// Launch (3 launches per call)
// ---------------------------------------------------------------------------
extern "C" void kernel_launch(void* const* d_in, const int* in_sizes, int n_in,
                              void* d_out, int out_size) {
    const float* emb      = (const float*)d_in[0];
    const int*   head_idx = (const int*)  d_in[1];
    const float* head_e   = (const float*)d_in[2];
    const int*   tail_idx = (const int*)  d_in[3];
    const float* tail_e   = (const float*)d_in[4];
    const float* adj      = (const float*)d_in[5];
    const float* relK     = (const float*)d_in[6];
    const float* selfK    = (const float*)d_in[7];
    float* out = (float*)d_out;

    cudaFuncSetAttribute(stage1_kernel,
                         cudaFuncAttributeMaxDynamicSharedMemorySize, SMEM_S1);
    cudaFuncSetAttribute(stage2_kernel,
                         cudaFuncAttributeMaxDynamicSharedMemorySize, SMEM_T);

    // 1) zero output + convert emb/e/relK/selfK
    prep_kernel<<<2048, 256>>>((float4*)out,
                               (const float2*)emb,
                               (const float2*)head_e,
                               (const float2*)tail_e,
                               (const float2*)relK,
                               (const float2*)selfK);
    // 2) stage1: dense per-node GEMM, register-fused fp32->fp16 A conversion
    stage1_kernel<<<256, 128, SMEM_S1>>>(adj);
    // 3) stage2: gathered fp16 GEMM (+ self term) -> out
    stage2_kernel<<<128, 128, SMEM_T>>>(head_idx, tail_idx, out);
}

// round 15
// speedup vs baseline: 6.2521x; 1.0597x over previous
#include <cuda_runtime.h>
#include <cuda_fp16.h>
#include <cstdint>
#include <cstddef>
#include <mma.h>

using namespace nvcuda;

// ---------------------------------------------------------------------------
// Problem: N=4096, D=128, R=8, OUT=128, B=4096
// Node-dedup + K-split restructuring:
//   compact: distinct nodes referenced by head_idx||tail_idx -> list (~3542)
//   stage1 (dense, reg-fused cvt, K-split 4):
//       upd_all[node][r*128+d] += sum_{n in split} adj[r,node,n]*emb[n,d]
//       (only for referenced nodes; fp16 atomic accumulation across splits)
//   stage2 (gather): out[m][o] = sum_k A2[m][k]*B2[k][o]
//       A2[m][k<1024] = upd_all[idx_m][k],  A2[m][1024+dd] = e_m[dd]
//       B2[k<1024][o] = relK_flat[k][o],    B2[1024+dd][o] = selfK[dd][o]
// Legacy wmma fp16 only (compute_103 PTX: no tcgen05).
// ---------------------------------------------------------------------------

#define NN    4096
#define DD    128
#define RR    8
#define OUTD  128
#define KU    (RR * DD)            // 1024
#define K2    (KU + DD)            // 1152

// Device-global scratch (no allocation):
__device__ __half g_emb_h[NN * DD];                // 1 MB
__device__ __half g_upd_h[(size_t)NN * KU];        // 8 MB  [node][r*128+d]
__device__ __half g_eh[(size_t)2 * NN * DD];       // 2 MB  [m][d] (head||tail)
__device__ __half g_Bh[K2 * OUTD];                 // 288 KB [k][o]
__device__ int    g_list[NN];                      // compacted node ids
__device__ int    g_cnt;                           // number of distinct nodes

__device__ __forceinline__ void cp_async16(uint32_t dst, const void* src) {
    asm volatile("cp.async.cg.shared.global [%0], [%1], 16;\n"
                 :: "r"(dst), "l"(src));
}
__device__ __forceinline__ void cp_commit() {
    asm volatile("cp.async.commit_group;\n" ::: "memory");
}

// ---------------------------------------------------------------------------
// Kernel 0: zero output + zero g_upd_h + convert emb/e/relK/selfK -> fp16
// grid 2048 x 256 = 524288 threads
// ---------------------------------------------------------------------------
__global__ void prep_kernel(float4* __restrict__ out,
                            const float2* __restrict__ emb2,
                            const float2* __restrict__ head_e2,
                            const float2* __restrict__ tail_e2,
                            const float2* __restrict__ relK2,
                            const float2* __restrict__ selfK2) {
    int i = blockIdx.x * blockDim.x + threadIdx.x;     // 0..524287
    if (i < 262144) out[i] = make_float4(0.f, 0.f, 0.f, 0.f);
    // zero g_upd_h: 8 MB = 524288 x 16 B
    {
        uint4 z = make_uint4(0u, 0u, 0u, 0u);
        ((uint4*)g_upd_h)[i] = z;
    }
    if (i < NN * DD / 2) {                             // emb
        float2 v = emb2[i];
        ((__half2*)g_emb_h)[i] = __floats2half2_rn(v.x, v.y);
    }
    if (i < 2 * NN * DD / 2) {                         // e (head||tail)
        float2 v = (i < NN * DD / 2) ? head_e2[i] : tail_e2[i - NN * DD / 2];
        ((__half2*)g_eh)[i] = __floats2half2_rn(v.x, v.y);
    }
    if (i < K2 * OUTD / 2) {                           // B2 (relK||selfK)
        float2 v = (i < KU * OUTD / 2) ? relK2[i] : selfK2[i - KU * OUTD / 2];
        ((__half2*)g_Bh)[i] = __floats2half2_rn(v.x, v.y);
    }
}

// ---------------------------------------------------------------------------
// Kernel 1: compact — build distinct-node list from head_idx||tail_idx.
// Single block, 1024 threads. Shared: 2 x 4096 ints (32 KB) scan buffers.
// ---------------------------------------------------------------------------
__global__ __launch_bounds__(1024) void compact_kernel(
    const int* __restrict__ head_idx,
    const int* __restrict__ tail_idx) {
    __shared__ int sA[NN];
    __shared__ int sB[NN];
    const int tid = threadIdx.x;

    // zero marks
#pragma unroll
    for (int k = 0; k < 4; k++) sA[tid + k * 1024] = 0;
    __syncthreads();
    // mark referenced nodes (benign write races: all store 1)
#pragma unroll
    for (int k = 0; k < 8; k++) {
        int q = tid + k * 1024;                 // 0..8191
        int v = (q < 4096) ? head_idx[q] : tail_idx[q - 4096];
        sA[v] = 1;
    }
    __syncthreads();
    // save own marks
    int m[4];
#pragma unroll
    for (int k = 0; k < 4; k++) m[k] = sA[tid + k * 1024];
    // inclusive Hillis-Steele scan, 12 steps, double-buffered
    int* src = sA;
    int* dst = sB;
    for (int off = 1; off < NN; off <<= 1) {
#pragma unroll
        for (int k = 0; k < 4; k++) {
            int i = tid + k * 1024;
            int v = src[i];
            if (i >= off) v += src[i - off];
            dst[i] = v;
        }
        __syncthreads();
        int* t = src; src = dst; dst = t;
    }
    // src holds inclusive scan
    int cnt = src[NN - 1];
#pragma unroll
    for (int k = 0; k < 4; k++) {
        int i = tid + k * 1024;
        int rank = src[i] - m[k];
        if (m[k]) g_list[rank] = i;
        if (i >= cnt) g_list[i] = 0;            // pad tail with a valid node
    }
    if (tid == 0) g_cnt = cnt;
}

// ---------------------------------------------------------------------------
// wmma fragment types
// ---------------------------------------------------------------------------
typedef wmma::fragment<wmma::matrix_a, 16, 16, 16, __half, wmma::row_major> HFragA;
typedef wmma::fragment<wmma::matrix_b, 16, 16, 16, __half, wmma::row_major> HFragB;
typedef wmma::fragment<wmma::accumulator, 16, 16, 16, float> HFragC;

// ---------------------------------------------------------------------------
// Kernel 2: stage1 dense GEMM, register-fused A conversion, K-split 4.
//   grid.x = 1024: tile = bx&31, r = (bx>>5)&7, split = bx>>8.
//   Rows = compacted nodes [tile*128, +128) (tail padded, stores guarded).
//   Per CTA: K = 1024 (n in [split*1024, +1024)), 32 iters of BK=32.
//   Epilogue: fp16 half2 atomicAdd into g_upd_h (zeroed in prep).
// SMEM: Ah 2 x 128 x 40 halves [0,20480); B16 3 x 32 x 136 halves
// [20480,46592). Epilogue reuses smem as 128x132 fp32 (67584 B = alloc).
// ---------------------------------------------------------------------------
#define AH_LD     40
#define AH_STG_B  10240
#define B16_LD    136
#define B16_STG_B 8704
#define OFF_AH    0
#define OFF_B16   20480
#define SMEM_S1   (128 * 132 * 4)       // 67584
#define S1_NIT    32                    // 1024 / 32

__global__ __launch_bounds__(128, 2) void stage1_kernel(
    const float* __restrict__ adj)       // [8,4096,4096] fp32
{
    extern __shared__ char smc[];
    __shared__ int nl[128];

    const int tid   = threadIdx.x;
    const int wid   = tid >> 5;
    const int bx    = blockIdx.x;
    const int tile  = bx & 31;
    const int r     = (bx >> 5) & 7;
    const int split = bx >> 8;
    const int node0 = tile * 128;

    const int cnt = g_cnt;
    if (node0 >= cnt) return;            // uniform early exit; CLC backfills

    nl[tid] = g_list[node0 + tid];
    __syncthreads();

    const uint32_t sm32 = (uint32_t)__cvta_generic_to_shared(smc);
    const int nbase = split * 1024;
    const float* adjrow = adj + ((size_t)r << 24) + (size_t)nl[tid] * NN + nbase;

    // B loader: 32 rows x 128 halves; 4 threads/row, 32 halves (64 B) each
    const int brow = tid >> 2;
    const int bh0  = (tid & 3) * 32;

    auto issueB = [&](int j) {
        const int s = j % 3;
        const int n0 = nbase + j * 32;
        const uint32_t b_dst = sm32 + OFF_B16 + (uint32_t)s * B16_STG_B
                             + (uint32_t)(brow * B16_LD + bh0) * 2;
        const __half* bsrc = g_emb_h + (size_t)(n0 + brow) * DD + bh0;
#pragma unroll
        for (int c = 0; c < 4; c++)
            cp_async16(b_dst + c * 16, bsrc + c * 8);
    };

    const int wm = (wid >> 1) * 64;
    const int wn = (wid & 1) * 64;

    HFragC acc[4][4];
#pragma unroll
    for (int i = 0; i < 4; i++)
#pragma unroll
        for (int j = 0; j < 4; j++) wmma::fill_fragment(acc[i][j], 0.0f);

    // prologue: A regs for iter 0; B stages 0,1
    float4 abuf[8];
#pragma unroll
    for (int q = 0; q < 8; q++) abuf[q] = *(const float4*)(adjrow + q * 4);
    issueB(0); cp_commit();
    issueB(1); cp_commit();

    for (int it = 0; it < S1_NIT; it++) {
        const int s = it % 3;
        asm volatile("cp.async.wait_group 1;\n" ::: "memory");   // B(it) arrived

        // convert abuf -> Ah[it&1], 32 halves = 4 x STS.128
        {
            __half* dst = (__half*)(smc + OFF_AH + (it & 1) * AH_STG_B)
                        + tid * AH_LD;
#pragma unroll
            for (int q = 0; q < 4; q++) {
                float4 v0 = abuf[2 * q];
                float4 v1 = abuf[2 * q + 1];
                __half2 h0 = __floats2half2_rn(v0.x, v0.y);
                __half2 h1 = __floats2half2_rn(v0.z, v0.w);
                __half2 h2 = __floats2half2_rn(v1.x, v1.y);
                __half2 h3 = __floats2half2_rn(v1.z, v1.w);
                uint4 w;
                w.x = *(const uint32_t*)&h0;
                w.y = *(const uint32_t*)&h1;
                w.z = *(const uint32_t*)&h2;
                w.w = *(const uint32_t*)&h3;
                *(uint4*)(dst + q * 8) = w;
            }
        }
        // register prefetch A for iter it+1
        if (it + 1 < S1_NIT) {
            const float* src = adjrow + (it + 1) * 32;
#pragma unroll
            for (int q = 0; q < 8; q++) abuf[q] = *(const float4*)(src + q * 4);
        }

        __syncthreads();   // publishes Ah[it&1] + B stage s; closes wmma_{it-1}

        if (it + 2 < S1_NIT) issueB(it + 2);
        cp_commit();

        const __half* Aw = (const __half*)(smc + OFF_AH + (it & 1) * AH_STG_B)
                         + wm * AH_LD;
        const __half* Bw = (const __half*)(smc + OFF_B16 + s * B16_STG_B) + wn;

#pragma unroll
        for (int ks = 0; ks < 2; ks++) {
            HFragA af[4];
            HFragB bf[4];
#pragma unroll
            for (int i = 0; i < 4; i++)
                wmma::load_matrix_sync(af[i], Aw + (i * 16) * AH_LD + ks * 16, AH_LD);
#pragma unroll
            for (int j = 0; j < 4; j++)
                wmma::load_matrix_sync(bf[j], Bw + (ks * 16) * B16_LD + j * 16, B16_LD);
#pragma unroll
            for (int i = 0; i < 4; i++)
#pragma unroll
                for (int j = 0; j < 4; j++)
                    wmma::mma_sync(acc[i][j], af[i], bf[j], acc[i][j]);
        }
    }

    // epilogue: C[128 node][128 d] -> half2 atomicAdd into g_upd_h
    __syncthreads();
    float* Csm = (float*)smc;            // 128 x 132 floats = 67584 B
#pragma unroll
    for (int i = 0; i < 4; i++)
#pragma unroll
        for (int j = 0; j < 4; j++)
            wmma::store_matrix_sync(Csm + (wm + i * 16) * 132 + (wn + j * 16),
                                    acc[i][j], 132, wmma::mem_row_major);
    __syncthreads();

    const int c  = tid & 63;             // half2 column
    const int r0 = (tid >> 6) * 64;      // row half
#pragma unroll
    for (int i = 0; i < 64; i++) {
        const int row = r0 + i;
        if (node0 + row < cnt) {
            __half2 v = __floats2half2_rn(Csm[row * 132 + 2 * c],
                                          Csm[row * 132 + 2 * c + 1]);
            atomicAdd((__half2*)(g_upd_h + (size_t)nl[row] * KU + (r << 7) + 2 * c), v);
        }
    }
}

// ---------------------------------------------------------------------------
// Kernel 3: stage2 gathered fp16 GEMM with folded self term (measured 23 us,
// unchanged from R14 — g_upd_h stays node-indexed).
// ---------------------------------------------------------------------------
#define BKH     64
#define LDAH    72
#define LDBH    136
#define ASTGH   (128 * LDAH)
#define BSTGH   (BKH * LDBH)
#define STGH    (ASTGH + BSTGH)
#define SMEM_T  (3 * STGH * 2)          // 107520 B

__global__ __launch_bounds__(128) void stage2_kernel(
    const int* __restrict__ head_idx,
    const int* __restrict__ tail_idx,
    float*     __restrict__ out)       // [8192,128]
{
    extern __shared__ __half smh[];
    __shared__ int rowidx[128];

    const int tid   = threadIdx.x;
    const int wid   = tid >> 5;
    const int bx    = blockIdx.x;
    const int tile  = bx & 63;
    const int split = bx >> 6;
    const int m0    = tile * 128;
    const int branch = tile >> 5;
    const int b0    = (tile & 31) * 128;

    const int* idxp = branch ? tail_idx : head_idx;
    rowidx[tid] = idxp[b0 + tid];
    __syncthreads();

    const uint32_t sm32 = (uint32_t)__cvta_generic_to_shared(smh);
    const size_t aoff_u = (size_t)rowidx[tid] * KU;
    const size_t aoff_e = (size_t)(m0 + tid) * DD;

    const int brow = tid >> 1;
    const int bh0  = (tid & 1) * 64;
    const int kstart = split * 576;

    auto issue = [&](int j) {
        const int s = j % 3;
        const int k0 = kstart + j * BKH;
        const uint32_t astage = sm32 + (uint32_t)(s * STGH * 2);
        const uint32_t bstage = astage + ASTGH * 2;
        const __half* asrc = (k0 < KU) ? (g_upd_h + aoff_u + k0)
                                       : (g_eh + aoff_e + (k0 - KU));
        const __half* bsrc = g_Bh + (size_t)(k0 + brow) * OUTD + bh0;
        const uint32_t a_dst = astage + (uint32_t)tid * (LDAH * 2);
        const uint32_t b_dst = bstage + (uint32_t)(brow * LDBH + bh0) * 2;
#pragma unroll
        for (int c = 0; c < 8; c++) {
            cp_async16(a_dst + c * 16, asrc + c * 8);
            cp_async16(b_dst + c * 16, bsrc + c * 8);
        }
    };

    const int wm = (wid >> 1) * 64;
    const int wn = (wid & 1) * 64;

    HFragC acc[4][4];
#pragma unroll
    for (int i = 0; i < 4; i++)
#pragma unroll
        for (int j = 0; j < 4; j++) wmma::fill_fragment(acc[i][j], 0.0f);

    issue(0); cp_commit();
    issue(1); cp_commit();

    const int NIT = 576 / BKH;   // 9
    for (int it = 0; it < NIT; it++) {
        const int s = it % 3;
        asm volatile("cp.async.wait_group 1;\n" ::: "memory");
        __syncthreads();
        if (it + 2 < NIT) issue(it + 2);
        cp_commit();

        const __half* As = smh + s * STGH;
        const __half* Bs = As + ASTGH;
        const __half* Aw = As + wm * LDAH;
        const __half* Bw = Bs + wn;

#pragma unroll
        for (int ks = 0; ks < 4; ks++) {
            HFragA af[4];
            HFragB bf[4];
#pragma unroll
            for (int i = 0; i < 4; i++)
                wmma::load_matrix_sync(af[i], Aw + (i * 16) * LDAH + ks * 16, LDAH);
#pragma unroll
            for (int j = 0; j < 4; j++)
                wmma::load_matrix_sync(bf[j], Bw + (ks * 16) * LDBH + j * 16, LDBH);
#pragma unroll
            for (int i = 0; i < 4; i++)
#pragma unroll
                for (int j = 0; j < 4; j++)
                    wmma::mma_sync(acc[i][j], af[i], bf[j], acc[i][j]);
        }
    }

    __syncthreads();
    float* Csm = (float*)smh;
#pragma unroll
    for (int i = 0; i < 4; i++)
#pragma unroll
        for (int j = 0; j < 4; j++)
            wmma::store_matrix_sync(Csm + (wm + i * 16) * 132 + (wn + j * 16),
                                    acc[i][j], 132, wmma::mem_row_major);
    __syncthreads();

#pragma unroll
    for (int i = 0; i < 128; i++)
        atomicAdd(&out[(size_t)(m0 + i) * OUTD + tid], Csm[i * 132 + tid]);
}

// ---------------------------------------------------------------------------
// Launch (4 launches per call)
// ---------------------------------------------------------------------------
extern "C" void kernel_launch(void* const* d_in, const int* in_sizes, int n_in,
                              void* d_out, int out_size) {
    const float* emb      = (const float*)d_in[0];
    const int*   head_idx = (const int*)  d_in[1];
    const float* head_e   = (const float*)d_in[2];
    const int*   tail_idx = (const int*)  d_in[3];
    const float* tail_e   = (const float*)d_in[4];
    const float* adj      = (const float*)d_in[5];
    const float* relK     = (const float*)d_in[6];
    const float* selfK    = (const float*)d_in[7];
    float* out = (float*)d_out;

    cudaFuncSetAttribute(stage1_kernel,
                         cudaFuncAttributeMaxDynamicSharedMemorySize, SMEM_S1);
    cudaFuncSetAttribute(stage2_kernel,
                         cudaFuncAttributeMaxDynamicSharedMemorySize, SMEM_T);

    // 1) zero output + zero g_upd_h + convert emb/e/relK/selfK
    prep_kernel<<<2048, 256>>>((float4*)out,
                               (const float2*)emb,
                               (const float2*)head_e,
                               (const float2*)tail_e,
                               (const float2*)relK,
                               (const float2*)selfK);
    // 2) compact distinct nodes
    compact_kernel<<<1, 1024>>>(head_idx, tail_idx);
    // 3) stage1: dense per-node GEMM, reg-fused cvt, K-split 4, compacted rows
    stage1_kernel<<<1024, 128, SMEM_S1>>>(adj);
    // 4) stage2: gathered fp16 GEMM (+ self term) -> out
    stage2_kernel<<<128, 128, SMEM_T>>>(head_idx, tail_idx, out);
}